// round 1
// baseline (speedup 1.0000x reference)
#include <cuda_runtime.h>
#include <math.h>

// Problem constants
#define NTOK  2048
#define HID   1024
#define ITR   2816
#define NEXP  8
#define NADP  2
#define RNK   16
#define TOPK  2
#define NSEQ  8
#define NPAIR (NTOK*TOPK)   // 4096

// GEMM tiling
#define BM 64
#define BN 64
#define BK 16
#define MAXT (NPAIR/BM + NEXP)  // 72 max row tiles across experts

// ---------------- device scratch (static, no allocation) ----------------
__device__ int   g_tok[NPAIR];
__device__ float g_w[NPAIR];
__device__ int   g_ad[NPAIR];
__device__ float g_scale[NPAIR];
__device__ int   g_rank[NPAIR];
__device__ int   g_exp[NPAIR];
__device__ int   g_slot[NPAIR];          // (n,k) -> sorted slot
__device__ int   g_ntiles;
__device__ int   g_tile_e[MAXT];
__device__ int   g_tile_m0[MAXT];
__device__ int   g_tile_rows[MAXT];
__device__ float g_zg[NPAIR*RNK];
__device__ float g_zu[NPAIR*RNK];
__device__ float g_zd[NPAIR*RNK];
__device__ float g_gu[(size_t)NPAIR*2*ITR];   // gate+up outputs (incl. lora)
__device__ float g_actbuf[(size_t)NPAIR*ITR]; // silu(g)*u
__device__ float g_pout[(size_t)NPAIR*HID];   // per-pair weighted down output

// ---------------- setup: sort pairs by expert, build tiles ----------------
__global__ void k_setup(const int* __restrict__ topk_ids,
                        const float* __restrict__ topk_w,
                        const int* __restrict__ widx,
                        const int* __restrict__ seq_lens,
                        const int* __restrict__ ranks,
                        const float* __restrict__ scalings)
{
    __shared__ int s_counts[NEXP];
    __shared__ int s_off[NEXP];
    __shared__ int s_cur[NEXP];
    __shared__ int s_cum[NSEQ];
    int tid = threadIdx.x;
    if (tid < NEXP) s_counts[tid] = 0;
    __syncthreads();
    for (int p = tid; p < NPAIR; p += blockDim.x)
        atomicAdd(&s_counts[topk_ids[p]], 1);
    __syncthreads();
    if (tid == 0) {
        int acc = 0;
        for (int e = 0; e < NEXP; e++) { s_off[e] = acc; s_cur[e] = acc; acc += s_counts[e]; }
        int c = 0;
        for (int s = 0; s < NSEQ; s++) { c += seq_lens[s]; s_cum[s] = c; }
        // tile descriptors
        int nt = 0;
        for (int e = 0; e < NEXP; e++) {
            int cnt = s_counts[e];
            for (int r0 = 0; r0 < cnt; r0 += BM) {
                g_tile_e[nt]    = e;
                g_tile_m0[nt]   = s_off[e] + r0;
                g_tile_rows[nt] = min(BM, cnt - r0);
                nt++;
            }
        }
        g_ntiles = nt;
    }
    __syncthreads();
    for (int p = tid; p < NPAIR; p += blockDim.x) {
        int n = p / TOPK;
        int e = topk_ids[p];
        int slot = atomicAdd(&s_cur[e], 1);
        g_tok[slot] = n;
        g_w[slot]   = topk_w[p];
        int s = 0;
        while (n >= s_cum[s]) s++;
        int a = widx[s];
        g_ad[slot]    = a;
        g_scale[slot] = scalings[a];
        g_rank[slot]  = ranks[a];
        g_exp[slot]   = e;
        g_slot[p]     = slot;
    }
}

// ---------------- LoRA input projections: zg, zu (rank-16 GEMV) ----------------
__global__ void k_lora_in(const float* __restrict__ x,
                          const float* __restrict__ gate_a,
                          const float* __restrict__ up_a)
{
    int slot = blockIdx.x;
    int tok  = g_tok[slot];
    int a    = g_ad[slot];
    int e    = g_exp[slot];
    int rank = g_rank[slot];
    __shared__ float xs[HID];
    int tid = threadIdx.x;
    for (int i = tid; i < HID; i += blockDim.x) xs[i] = x[(size_t)tok*HID + i];
    __syncthreads();
    int warp = tid >> 5, lane = tid & 31;
    for (int r = warp; r < RNK; r += 8) {
        const float* ga = gate_a + ((size_t)((a*NEXP + e)*RNK) + r)*HID;
        const float* ua = up_a   + ((size_t)((a*NEXP + e)*RNK) + r)*HID;
        float a0 = 0.f, a1 = 0.f;
        for (int h = lane; h < HID; h += 32) { a0 += xs[h]*ga[h]; a1 += xs[h]*ua[h]; }
        #pragma unroll
        for (int o = 16; o; o >>= 1) {
            a0 += __shfl_down_sync(0xffffffffu, a0, o);
            a1 += __shfl_down_sync(0xffffffffu, a1, o);
        }
        if (lane == 0) {
            g_zg[slot*RNK + r] = (r < rank) ? a0 : 0.f;
            g_zu[slot*RNK + r] = (r < rank) ? a1 : 0.f;
        }
    }
}

// ---------------- GEMM1: gu[slot, j] = x @ Wgu[e]^T + scale * (z @ B^T) ----------------
__global__ void k_gemm1(const float* __restrict__ x,
                        const float* __restrict__ Wgu,
                        const float* __restrict__ gb,
                        const float* __restrict__ ub)
{
    int t = blockIdx.x;
    if (t >= g_ntiles) return;
    int e = g_tile_e[t], m0 = g_tile_m0[t], rows = g_tile_rows[t];
    int j0 = blockIdx.y * BN;

    __shared__ float Xs[BK][BM];
    __shared__ float Ws[BK][BN];
    __shared__ int   toks[BM];

    int tid = threadIdx.x;
    if (tid < BM) toks[tid] = (tid < rows) ? g_tok[m0 + tid] : -1;
    __syncthreads();

    const float* Wb = Wgu + (size_t)e*(2*ITR)*HID + (size_t)j0*HID;
    float acc[4][4];
    #pragma unroll
    for (int i = 0; i < 4; i++)
        #pragma unroll
        for (int j = 0; j < 4; j++) acc[i][j] = 0.f;

    int tx = tid & 15, ty = tid >> 4;
    int lr = tid >> 2, lq = tid & 3;
    int tk = toks[lr];
    const float* xrow = (tk >= 0) ? (x + (size_t)tk*HID) : 0;
    const float* wrow = Wb + (size_t)lr*HID;

    for (int k0 = 0; k0 < HID; k0 += BK) {
        float4 xv = make_float4(0.f,0.f,0.f,0.f);
        if (xrow) xv = *(const float4*)(xrow + k0 + lq*4);
        float4 wv = *(const float4*)(wrow + k0 + lq*4);
        Xs[lq*4+0][lr]=xv.x; Xs[lq*4+1][lr]=xv.y; Xs[lq*4+2][lr]=xv.z; Xs[lq*4+3][lr]=xv.w;
        Ws[lq*4+0][lr]=wv.x; Ws[lq*4+1][lr]=wv.y; Ws[lq*4+2][lr]=wv.z; Ws[lq*4+3][lr]=wv.w;
        __syncthreads();
        #pragma unroll
        for (int kk = 0; kk < BK; kk++) {
            float4 a4 = *(const float4*)&Xs[kk][ty*4];
            float4 b4 = *(const float4*)&Ws[kk][tx*4];
            float av[4] = {a4.x, a4.y, a4.z, a4.w};
            float bv[4] = {b4.x, b4.y, b4.z, b4.w};
            #pragma unroll
            for (int i = 0; i < 4; i++)
                #pragma unroll
                for (int j = 0; j < 4; j++) acc[i][j] += av[i]*bv[j];
        }
        __syncthreads();
    }

    bool isGate = (j0 < ITR);
    const float* B   = isGate ? gb : ub;
    int jb0          = isGate ? j0 : (j0 - ITR);
    #pragma unroll
    for (int i = 0; i < 4; i++) {
        int m = ty*4 + i;
        if (m >= rows) continue;
        int slot = m0 + m;
        float sc = g_scale[slot];
        int a    = g_ad[slot];
        const float* z = (isGate ? g_zg : g_zu) + slot*RNK;
        float zr[RNK];
        #pragma unroll
        for (int r = 0; r < RNK; r++) zr[r] = z[r];
        const float* Bbase = B + ((size_t)(a*NEXP + e)*ITR + jb0)*RNK;
        float* orow = g_gu + (size_t)slot*(2*ITR) + j0;
        #pragma unroll
        for (int j = 0; j < 4; j++) {
            int jj = tx*4 + j;
            const float* Br = Bbase + (size_t)jj*RNK;
            float l = 0.f;
            #pragma unroll
            for (int r = 0; r < RNK; r++) l += zr[r]*Br[r];
            orow[jj] = acc[i][j] + sc*l;
        }
    }
}

// ---------------- act = silu(gate) * up ----------------
__global__ void k_act()
{
    const size_t total = (size_t)NPAIR*ITR/4;
    for (size_t idx = (size_t)blockIdx.x*blockDim.x + threadIdx.x; idx < total;
         idx += (size_t)gridDim.x*blockDim.x) {
        size_t p  = idx / (ITR/4);
        size_t i4 = idx % (ITR/4);
        const float4 g = *(const float4*)(g_gu + p*(2*ITR) + i4*4);
        const float4 u = *(const float4*)(g_gu + p*(2*ITR) + ITR + i4*4);
        float4 o;
        o.x = g.x/(1.f + expf(-g.x)) * u.x;
        o.y = g.y/(1.f + expf(-g.y)) * u.y;
        o.z = g.z/(1.f + expf(-g.z)) * u.z;
        o.w = g.w/(1.f + expf(-g.w)) * u.w;
        *(float4*)(g_actbuf + p*ITR + i4*4) = o;
    }
}

// ---------------- LoRA mid projection: zd ----------------
__global__ void k_lora_mid(const float* __restrict__ down_a)
{
    int slot = blockIdx.x;
    int a    = g_ad[slot];
    int e    = g_exp[slot];
    int rank = g_rank[slot];
    __shared__ float as[ITR];
    int tid = threadIdx.x;
    for (int i = tid; i < ITR; i += blockDim.x) as[i] = g_actbuf[(size_t)slot*ITR + i];
    __syncthreads();
    int warp = tid >> 5, lane = tid & 31;
    for (int r = warp; r < RNK; r += 8) {
        const float* da = down_a + ((size_t)((a*NEXP + e)*RNK) + r)*ITR;
        float acc = 0.f;
        for (int i = lane; i < ITR; i += 32) acc += as[i]*da[i];
        #pragma unroll
        for (int o = 16; o; o >>= 1) acc += __shfl_down_sync(0xffffffffu, acc, o);
        if (lane == 0) g_zd[slot*RNK + r] = (r < rank) ? acc : 0.f;
    }
}

// ---------------- GEMM2: pout[slot,h] = w * (act @ Wd[e]^T + scale*(zd @ db^T)) ----------------
__global__ void k_gemm2(const float* __restrict__ Wd,
                        const float* __restrict__ db)
{
    int t = blockIdx.x;
    if (t >= g_ntiles) return;
    int e = g_tile_e[t], m0 = g_tile_m0[t], rows = g_tile_rows[t];
    int h0 = blockIdx.y * BN;

    __shared__ float Xs[BK][BM];
    __shared__ float Ws[BK][BN];

    int tid = threadIdx.x;
    const float* Wb = Wd + (size_t)e*HID*ITR + (size_t)h0*ITR;
    float acc[4][4];
    #pragma unroll
    for (int i = 0; i < 4; i++)
        #pragma unroll
        for (int j = 0; j < 4; j++) acc[i][j] = 0.f;

    int tx = tid & 15, ty = tid >> 4;
    int lr = tid >> 2, lq = tid & 3;
    const float* xrow = (lr < rows) ? (g_actbuf + (size_t)(m0 + lr)*ITR) : 0;
    const float* wrow = Wb + (size_t)lr*ITR;

    for (int k0 = 0; k0 < ITR; k0 += BK) {
        float4 xv = make_float4(0.f,0.f,0.f,0.f);
        if (xrow) xv = *(const float4*)(xrow + k0 + lq*4);
        float4 wv = *(const float4*)(wrow + k0 + lq*4);
        Xs[lq*4+0][lr]=xv.x; Xs[lq*4+1][lr]=xv.y; Xs[lq*4+2][lr]=xv.z; Xs[lq*4+3][lr]=xv.w;
        Ws[lq*4+0][lr]=wv.x; Ws[lq*4+1][lr]=wv.y; Ws[lq*4+2][lr]=wv.z; Ws[lq*4+3][lr]=wv.w;
        __syncthreads();
        #pragma unroll
        for (int kk = 0; kk < BK; kk++) {
            float4 a4 = *(const float4*)&Xs[kk][ty*4];
            float4 b4 = *(const float4*)&Ws[kk][tx*4];
            float av[4] = {a4.x, a4.y, a4.z, a4.w};
            float bv[4] = {b4.x, b4.y, b4.z, b4.w};
            #pragma unroll
            for (int i = 0; i < 4; i++)
                #pragma unroll
                for (int j = 0; j < 4; j++) acc[i][j] += av[i]*bv[j];
        }
        __syncthreads();
    }

    #pragma unroll
    for (int i = 0; i < 4; i++) {
        int m = ty*4 + i;
        if (m >= rows) continue;
        int slot = m0 + m;
        float sc = g_scale[slot];
        float w  = g_w[slot];
        int a    = g_ad[slot];
        const float* z = g_zd + slot*RNK;
        float zr[RNK];
        #pragma unroll
        for (int r = 0; r < RNK; r++) zr[r] = z[r];
        const float* Bbase = db + ((size_t)(a*NEXP + e)*HID + h0)*RNK;
        float* orow = g_pout + (size_t)slot*HID + h0;
        #pragma unroll
        for (int j = 0; j < 4; j++) {
            int hh = tx*4 + j;
            const float* Br = Bbase + (size_t)hh*RNK;
            float l = 0.f;
            #pragma unroll
            for (int r = 0; r < RNK; r++) l += zr[r]*Br[r];
            orow[hh] = w * (acc[i][j] + sc*l);
        }
    }
}

// ---------------- combine two pairs per token ----------------
__global__ void k_combine(float* __restrict__ out)
{
    int n = blockIdx.x;
    int s0 = g_slot[n*TOPK + 0];
    int s1 = g_slot[n*TOPK + 1];
    int tid = threadIdx.x;                       // HID/4 == 256
    const float4 a = ((const float4*)(g_pout + (size_t)s0*HID))[tid];
    const float4 b = ((const float4*)(g_pout + (size_t)s1*HID))[tid];
    ((float4*)(out + (size_t)n*HID))[tid] = make_float4(a.x+b.x, a.y+b.y, a.z+b.z, a.w+b.w);
}

// ---------------- launch ----------------
extern "C" void kernel_launch(void* const* d_in, const int* in_sizes, int n_in,
                              void* d_out, int out_size)
{
    const float* x        = (const float*)d_in[0];
    const int*   topk_ids = (const int*)  d_in[1];
    const float* topk_w   = (const float*)d_in[2];
    const float* gate_a   = (const float*)d_in[3];
    const float* gate_b   = (const float*)d_in[4];
    const float* up_a     = (const float*)d_in[5];
    const float* up_b     = (const float*)d_in[6];
    const float* down_a   = (const float*)d_in[7];
    const float* down_b   = (const float*)d_in[8];
    const int*   widx     = (const int*)  d_in[9];
    const int*   seq_lens = (const int*)  d_in[10];
    const int*   ranks    = (const int*)  d_in[11];
    const float* scalings = (const float*)d_in[12];
    const float* Wgu      = (const float*)d_in[13];
    const float* Wd       = (const float*)d_in[14];
    float* out = (float*)d_out;

    k_setup<<<1, 256>>>(topk_ids, topk_w, widx, seq_lens, ranks, scalings);
    k_lora_in<<<NPAIR, 256>>>(x, gate_a, up_a);
    k_gemm1<<<dim3(MAXT, (2*ITR)/BN), 256>>>(x, Wgu, gate_b, up_b);
    k_act<<<4096, 256>>>();
    k_lora_mid<<<NPAIR, 256>>>(down_a);
    k_gemm2<<<dim3(MAXT, HID/BN), 256>>>(Wd, down_b);
    k_combine<<<NTOK, 256>>>(out);
}

// round 3
// speedup vs baseline: 2.4189x; 2.4189x over previous
#include <cuda_runtime.h>
#include <math.h>
#include <stdint.h>

// ---------------- problem constants ----------------
#define NTOK  2048
#define HID   1024
#define ITR   2816
#define NEXP  8
#define NADP  2
#define RNK   16
#define TOPK  2
#define NSEQ  8
#define NPAIR (NTOK*TOPK)        // 4096
#define NPAD  (NPAIR + 128)

// ---------------- GEMM tiling (mma.sync m16n8k8 tf32) ----------------
#define BM 128
#define BN 128
#define BKC 32                    // fp32 K elements per chunk
#define SAST 36                   // smem row stride in floats (conflict-free)
#define SAF (BM*SAST)             // 4608 floats per operand tile
#define STAGEF (2*SAF)            // 9216 floats per stage (A+B)
#define SMEM_DYN (2*STAGEF*4)     // 73728 bytes (2 stages)
#define NK1 (HID/BKC)             // 32
#define NK2 (ITR/BKC)             // 88
#define MAXT (NPAIR/BM + NEXP)    // 40
#define NCT1 ((2*ITR)/BN)         // 44
#define NCT2 (HID/BN)             // 8

// ---------------- device scratch ----------------
__device__ int   g_tok[NPAIR];
__device__ float g_w[NPAIR];
__device__ int   g_ad[NPAIR];
__device__ float g_scale[NPAIR];
__device__ int   g_rank[NPAIR];
__device__ int   g_exp[NPAIR];
__device__ int   g_slot[NPAIR];
__device__ int   g2_ntiles;
__device__ int   g2_e[MAXT];
__device__ int   g2_m0[MAXT];
__device__ int   g2_rows[MAXT];
__device__ float g_zg[NPAIR*RNK];
__device__ float g_zu[NPAIR*RNK];
__device__ float g_zd[NPAIR*RNK];
__device__ float g_xg[(size_t)NPAD*HID];       // gathered x rows by slot
__device__ float g_act[(size_t)NPAD*ITR];      // silu(g)*u (fp32)
__device__ float g_gu[(size_t)NPAIR*2*ITR];    // gate|up outputs
__device__ float g_pout[(size_t)NPAIR*HID];    // per-pair weighted down out

// ---------------- helpers ----------------
__device__ __forceinline__ float f2tf(float x){
    uint32_t u;
    asm("cvt.rna.tf32.f32 %0, %1;" : "=r"(u) : "f"(x));
    return __uint_as_float(u);
}
__device__ __forceinline__ void mma8(float* c, const uint32_t* a, const uint32_t* b){
    asm volatile("mma.sync.aligned.m16n8k8.row.col.f32.tf32.tf32.f32 "
        "{%0,%1,%2,%3}, {%4,%5,%6,%7}, {%8,%9}, {%0,%1,%2,%3};"
        : "+f"(c[0]), "+f"(c[1]), "+f"(c[2]), "+f"(c[3])
        : "r"(a[0]), "r"(a[1]), "r"(a[2]), "r"(a[3]), "r"(b[0]), "r"(b[1]));
}

// ---------------- mainloop: C[128x128] += A[128xK] * B[128xK]^T ----------------
__device__ __forceinline__ void gemm_core(const float* __restrict__ Ab, int lda,
                                          const float* __restrict__ Bb, int ldb,
                                          int nk, float* smf, float (*acc)[4][4])
{
    int tid = threadIdx.x, lane = tid & 31, wid = tid >> 5;
    int wm = wid & 1, wn = wid >> 1;
    int g = lane >> 2, tg = lane & 3;
    int rb = tid >> 3, cb = (tid & 7) * 4;

    float* Ast[2] = { smf, smf + STAGEF };
    float* Bst[2] = { smf + SAF, smf + STAGEF + SAF };
    float4 pa[4], pb[4];

    #pragma unroll
    for (int q = 0; q < 4; q++){
        pa[q] = *(const float4*)(Ab + (size_t)(rb + 32*q)*lda + cb);
        pb[q] = *(const float4*)(Bb + (size_t)(rb + 32*q)*ldb + cb);
    }
    #pragma unroll
    for (int q = 0; q < 4; q++){
        float* d = Ast[0] + (rb + 32*q)*SAST + cb;
        d[0]=f2tf(pa[q].x); d[1]=f2tf(pa[q].y); d[2]=f2tf(pa[q].z); d[3]=f2tf(pa[q].w);
        float* e2 = Bst[0] + (rb + 32*q)*SAST + cb;
        e2[0]=f2tf(pb[q].x); e2[1]=f2tf(pb[q].y); e2[2]=f2tf(pb[q].z); e2[3]=f2tf(pb[q].w);
    }
    __syncthreads();

    for (int kc = 0; kc < nk; kc++){
        if (kc + 1 < nk){
            int kof = (kc + 1)*BKC;
            #pragma unroll
            for (int q = 0; q < 4; q++){
                pa[q] = *(const float4*)(Ab + (size_t)(rb + 32*q)*lda + kof + cb);
                pb[q] = *(const float4*)(Bb + (size_t)(rb + 32*q)*ldb + kof + cb);
            }
        }
        const float* As = Ast[kc & 1];
        const float* Bs = Bst[kc & 1];
        #pragma unroll
        for (int ks = 0; ks < 4; ks++){
            int k0 = ks*8;
            uint32_t ar[4][4], br[4][2];
            #pragma unroll
            for (int mf = 0; mf < 4; mf++){
                const float* ap = As + (wm*64 + mf*16 + g)*SAST + k0 + tg;
                ar[mf][0] = __float_as_uint(ap[0]);
                ar[mf][1] = __float_as_uint(ap[8*SAST]);
                ar[mf][2] = __float_as_uint(ap[4]);
                ar[mf][3] = __float_as_uint(ap[8*SAST + 4]);
            }
            #pragma unroll
            for (int nf = 0; nf < 4; nf++){
                const float* bp = Bs + (wn*32 + nf*8 + g)*SAST + k0 + tg;
                br[nf][0] = __float_as_uint(bp[0]);
                br[nf][1] = __float_as_uint(bp[4]);
            }
            #pragma unroll
            for (int mf = 0; mf < 4; mf++)
                #pragma unroll
                for (int nf = 0; nf < 4; nf++)
                    mma8(acc[mf][nf], ar[mf], br[nf]);
        }
        __syncthreads();
        if (kc + 1 < nk){
            int s = (kc + 1) & 1;
            #pragma unroll
            for (int q = 0; q < 4; q++){
                float* d = Ast[s] + (rb + 32*q)*SAST + cb;
                d[0]=f2tf(pa[q].x); d[1]=f2tf(pa[q].y); d[2]=f2tf(pa[q].z); d[3]=f2tf(pa[q].w);
                float* e2 = Bst[s] + (rb + 32*q)*SAST + cb;
                e2[0]=f2tf(pb[q].x); e2[1]=f2tf(pb[q].y); e2[2]=f2tf(pb[q].z); e2[3]=f2tf(pb[q].w);
            }
            __syncthreads();
        }
    }
}

// ---------------- setup ----------------
__global__ void k_setup(const int* __restrict__ topk_ids, const float* __restrict__ topk_w,
                        const int* __restrict__ widx, const int* __restrict__ seq_lens,
                        const int* __restrict__ ranks, const float* __restrict__ scalings)
{
    __shared__ int cnt[NEXP*NADP], off[NEXP*NADP], cur[NEXP*NADP], cum[NSEQ];
    int tid = threadIdx.x;
    if (tid < NEXP*NADP) cnt[tid] = 0;
    __syncthreads();
    if (tid == 0){ int c = 0; for (int s = 0; s < NSEQ; s++){ c += seq_lens[s]; cum[s] = c; } }
    __syncthreads();
    for (int p = tid; p < NPAIR; p += blockDim.x){
        int n = p / TOPK; int e = topk_ids[p];
        int s = 0; while (n >= cum[s]) s++;
        atomicAdd(&cnt[e*NADP + widx[s]], 1);
    }
    __syncthreads();
    if (tid == 0){
        int acc = 0;
        for (int k = 0; k < NEXP*NADP; k++){ off[k] = acc; cur[k] = acc; acc += cnt[k]; }
        int nt = 0;
        for (int e = 0; e < NEXP; e++){
            int base = off[e*NADP];
            int c = cnt[e*NADP] + cnt[e*NADP+1];
            for (int r0 = 0; r0 < c; r0 += BM){
                g2_e[nt] = e; g2_m0[nt] = base + r0; g2_rows[nt] = min(BM, c - r0); nt++;
            }
        }
        g2_ntiles = nt;
    }
    __syncthreads();
    for (int p = tid; p < NPAIR; p += blockDim.x){
        int n = p / TOPK; int e = topk_ids[p];
        int s = 0; while (n >= cum[s]) s++;
        int a = widx[s];
        int slot = atomicAdd(&cur[e*NADP + a], 1);
        g_tok[slot] = n; g_w[slot] = topk_w[p]; g_ad[slot] = a;
        g_scale[slot] = scalings[a]; g_rank[slot] = ranks[a]; g_exp[slot] = e;
        g_slot[p] = slot;
    }
}

// ---------------- LoRA in-projection + gather x ----------------
__global__ void k_lora_in(const float* __restrict__ x,
                          const float* __restrict__ gate_a,
                          const float* __restrict__ up_a)
{
    int slot = blockIdx.x;
    int tok = g_tok[slot], a = g_ad[slot], e = g_exp[slot], rank = g_rank[slot];
    __shared__ float xs[HID];
    int tid = threadIdx.x;
    for (int i = tid; i < HID; i += blockDim.x){
        float v = x[(size_t)tok*HID + i];
        xs[i] = v;
        g_xg[(size_t)slot*HID + i] = v;
    }
    __syncthreads();
    int warp = tid >> 5, lane = tid & 31;
    for (int r = warp; r < RNK; r += 8){
        const float* ga = gate_a + ((size_t)((a*NEXP + e)*RNK) + r)*HID;
        const float* ua = up_a   + ((size_t)((a*NEXP + e)*RNK) + r)*HID;
        float a0 = 0.f, a1 = 0.f;
        for (int h = lane; h < HID; h += 32){ a0 += xs[h]*ga[h]; a1 += xs[h]*ua[h]; }
        #pragma unroll
        for (int o = 16; o; o >>= 1){
            a0 += __shfl_down_sync(0xffffffffu, a0, o);
            a1 += __shfl_down_sync(0xffffffffu, a1, o);
        }
        if (lane == 0){
            g_zg[slot*RNK + r] = (r < rank) ? a0 : 0.f;
            g_zu[slot*RNK + r] = (r < rank) ? a1 : 0.f;
        }
    }
}

// ---------------- GEMM1: g_gu = X @ Wgu^T + scale * z @ B^T ----------------
__global__ __launch_bounds__(256, 1) void k_gemm1(const float* __restrict__ Wgu,
                                                  const float* __restrict__ gb,
                                                  const float* __restrict__ ub)
{
    int t = blockIdx.x;
    if (t >= g2_ntiles) return;
    int e = g2_e[t], m0 = g2_m0[t], rows = g2_rows[t];
    int j0 = blockIdx.y * BN;
    bool isGate = (j0 < ITR);

    extern __shared__ float smf[];
    __shared__ float s_scale[BM];
    __shared__ int   s_ad[BM];

    float acc[4][4][4];
    #pragma unroll
    for (int i = 0; i < 4; i++)
        #pragma unroll
        for (int j = 0; j < 4; j++)
            #pragma unroll
            for (int k = 0; k < 4; k++) acc[i][j][k] = 0.f;

    const float* Ab = g_xg + (size_t)m0*HID;
    const float* Bb = Wgu + (size_t)e*(2*ITR)*HID + (size_t)j0*HID;
    gemm_core(Ab, HID, Bb, HID, NK1, smf, acc);

    // stage LoRA B rows + z into smem
    int tid = threadIdx.x, lane = tid & 31, wid = tid >> 5;
    float* blsm = smf;               // [2][128][16] = 4096 floats
    float* zsm  = smf + 4096;        // [128][16]    = 2048 floats
    const float* Bl = isGate ? gb : ub;
    int c0g = isGate ? j0 : (j0 - ITR);
    #pragma unroll
    for (int q = 0; q < 4; q++){
        int idx = tid + q*256;       // 0..1023
        int a = idx >> 9, rem = idx & 511, col = rem >> 2, f = rem & 3;
        *(float4*)(blsm + (size_t)idx*4) =
            *(const float4*)(Bl + ((size_t)(a*NEXP + e)*ITR + c0g + col)*RNK + f*4);
    }
    const float* zsrc = isGate ? g_zg : g_zu;
    #pragma unroll
    for (int q = 0; q < 2; q++){
        int idx = tid + q*256;       // 0..511
        int row = idx >> 2, f = idx & 3;
        int slot = m0 + row; if (slot >= NPAIR) slot = NPAIR - 1;
        *(float4*)(zsm + (size_t)idx*4) = *(const float4*)(zsrc + (size_t)slot*RNK + f*4);
    }
    if (tid < BM){
        int slot = min(m0 + tid, NPAIR - 1);
        s_scale[tid] = g_scale[slot]; s_ad[tid] = g_ad[slot];
    }
    __syncthreads();

    int wm = wid & 1, wn = wid >> 1, g = lane >> 2, tg = lane & 3;
    #pragma unroll
    for (int mf = 0; mf < 4; mf++){
        #pragma unroll
        for (int h = 0; h < 2; h++){
            int row = wm*64 + mf*16 + g + h*8;
            if (row >= rows) continue;
            float sc = s_scale[row]; int a = s_ad[row];
            const float* zr = zsm + row*16;
            float z[16];
            #pragma unroll
            for (int r = 0; r < 16; r += 4){
                float4 v = *(const float4*)(zr + r);
                z[r]=v.x; z[r+1]=v.y; z[r+2]=v.z; z[r+3]=v.w;
            }
            float* orow = g_gu + (size_t)(m0 + row)*(2*ITR) + j0;
            #pragma unroll
            for (int nf = 0; nf < 4; nf++){
                #pragma unroll
                for (int p = 0; p < 2; p++){
                    int cn = wn*32 + nf*8 + 2*tg + p;
                    const float* bl = blsm + (size_t)(a*BM + cn)*16;
                    float l = 0.f;
                    #pragma unroll
                    for (int r = 0; r < 16; r++) l += z[r]*bl[r];
                    orow[cn] = acc[mf][nf][h*2 + p] + sc*l;
                }
            }
        }
    }
}

// ---------------- act = silu(gate)*up (fp32) ----------------
__global__ void k_act()
{
    const size_t total = (size_t)NPAIR*(ITR/4);
    for (size_t idx = (size_t)blockIdx.x*blockDim.x + threadIdx.x; idx < total;
         idx += (size_t)gridDim.x*blockDim.x){
        size_t p = idx / (ITR/4);
        size_t i4 = idx % (ITR/4);
        const float4 g = *(const float4*)(g_gu + p*(2*ITR) + i4*4);
        const float4 u = *(const float4*)(g_gu + p*(2*ITR) + ITR + i4*4);
        float4 o;
        o.x = g.x/(1.f + expf(-g.x)) * u.x;
        o.y = g.y/(1.f + expf(-g.y)) * u.y;
        o.z = g.z/(1.f + expf(-g.z)) * u.z;
        o.w = g.w/(1.f + expf(-g.w)) * u.w;
        *(float4*)(g_act + p*ITR + i4*4) = o;
    }
}

// ---------------- LoRA mid-projection zd ----------------
__global__ void k_lora_mid(const float* __restrict__ down_a)
{
    int slot = blockIdx.x;
    int a = g_ad[slot], e = g_exp[slot], rank = g_rank[slot];
    __shared__ float as[ITR];
    int tid = threadIdx.x;
    for (int i = tid; i < ITR; i += blockDim.x) as[i] = g_act[(size_t)slot*ITR + i];
    __syncthreads();
    int warp = tid >> 5, lane = tid & 31;
    for (int r = warp; r < RNK; r += 8){
        const float* da = down_a + ((size_t)((a*NEXP + e)*RNK) + r)*ITR;
        float acc = 0.f;
        for (int i = lane; i < ITR; i += 32) acc += as[i]*da[i];
        #pragma unroll
        for (int o = 16; o; o >>= 1) acc += __shfl_down_sync(0xffffffffu, acc, o);
        if (lane == 0) g_zd[slot*RNK + r] = (r < rank) ? acc : 0.f;
    }
}

// ---------------- GEMM2: pout = w*(act @ Wd^T + scale * zd @ db^T) ----------------
__global__ __launch_bounds__(256, 1) void k_gemm2(const float* __restrict__ Wd,
                                                  const float* __restrict__ db)
{
    int t = blockIdx.x;
    if (t >= g2_ntiles) return;
    int e = g2_e[t], m0 = g2_m0[t], rows = g2_rows[t];
    int j0 = blockIdx.y * BN;

    extern __shared__ float smf[];
    __shared__ float s_scale[BM];
    __shared__ float s_wt[BM];
    __shared__ int   s_ad[BM];

    float acc[4][4][4];
    #pragma unroll
    for (int i = 0; i < 4; i++)
        #pragma unroll
        for (int j = 0; j < 4; j++)
            #pragma unroll
            for (int k = 0; k < 4; k++) acc[i][j][k] = 0.f;

    const float* Ab = g_act + (size_t)m0*ITR;
    const float* Bb = Wd + (size_t)e*HID*ITR + (size_t)j0*ITR;
    gemm_core(Ab, ITR, Bb, ITR, NK2, smf, acc);

    int tid = threadIdx.x, lane = tid & 31, wid = tid >> 5;
    float* blsm = smf;
    float* zsm  = smf + 4096;
    #pragma unroll
    for (int q = 0; q < 4; q++){
        int idx = tid + q*256;
        int a = idx >> 9, rem = idx & 511, col = rem >> 2, f = rem & 3;
        *(float4*)(blsm + (size_t)idx*4) =
            *(const float4*)(db + ((size_t)(a*NEXP + e)*HID + j0 + col)*RNK + f*4);
    }
    #pragma unroll
    for (int q = 0; q < 2; q++){
        int idx = tid + q*256;
        int row = idx >> 2, f = idx & 3;
        int slot = m0 + row; if (slot >= NPAIR) slot = NPAIR - 1;
        *(float4*)(zsm + (size_t)idx*4) = *(const float4*)(g_zd + (size_t)slot*RNK + f*4);
    }
    if (tid < BM){
        int slot = min(m0 + tid, NPAIR - 1);
        s_scale[tid] = g_scale[slot]; s_ad[tid] = g_ad[slot]; s_wt[tid] = g_w[slot];
    }
    __syncthreads();

    int wm = wid & 1, wn = wid >> 1, g = lane >> 2, tg = lane & 3;
    #pragma unroll
    for (int mf = 0; mf < 4; mf++){
        #pragma unroll
        for (int h = 0; h < 2; h++){
            int row = wm*64 + mf*16 + g + h*8;
            if (row >= rows) continue;
            float sc = s_scale[row]; float w = s_wt[row]; int a = s_ad[row];
            const float* zr = zsm + row*16;
            float z[16];
            #pragma unroll
            for (int r = 0; r < 16; r += 4){
                float4 v = *(const float4*)(zr + r);
                z[r]=v.x; z[r+1]=v.y; z[r+2]=v.z; z[r+3]=v.w;
            }
            float* orow = g_pout + (size_t)(m0 + row)*HID + j0;
            #pragma unroll
            for (int nf = 0; nf < 4; nf++){
                #pragma unroll
                for (int p = 0; p < 2; p++){
                    int cn = wn*32 + nf*8 + 2*tg + p;
                    const float* bl = blsm + (size_t)(a*BM + cn)*16;
                    float l = 0.f;
                    #pragma unroll
                    for (int r = 0; r < 16; r++) l += z[r]*bl[r];
                    orow[cn] = w * (acc[mf][nf][h*2 + p] + sc*l);
                }
            }
        }
    }
}

// ---------------- combine ----------------
__global__ void k_combine(float* __restrict__ out)
{
    int n = blockIdx.x;
    int s0 = g_slot[n*TOPK + 0];
    int s1 = g_slot[n*TOPK + 1];
    int tid = threadIdx.x;   // HID/4 == 256
    const float4 a = ((const float4*)(g_pout + (size_t)s0*HID))[tid];
    const float4 b = ((const float4*)(g_pout + (size_t)s1*HID))[tid];
    ((float4*)(out + (size_t)n*HID))[tid] = make_float4(a.x+b.x, a.y+b.y, a.z+b.z, a.w+b.w);
}

// ---------------- launch ----------------
extern "C" void kernel_launch(void* const* d_in, const int* in_sizes, int n_in,
                              void* d_out, int out_size)
{
    const float* x        = (const float*)d_in[0];
    const int*   topk_ids = (const int*)  d_in[1];
    const float* topk_w   = (const float*)d_in[2];
    const float* gate_a   = (const float*)d_in[3];
    const float* gate_b   = (const float*)d_in[4];
    const float* up_a     = (const float*)d_in[5];
    const float* up_b     = (const float*)d_in[6];
    const float* down_a   = (const float*)d_in[7];
    const float* down_b   = (const float*)d_in[8];
    const int*   widx     = (const int*)  d_in[9];
    const int*   seq_lens = (const int*)  d_in[10];
    const int*   ranks    = (const int*)  d_in[11];
    const float* scalings = (const float*)d_in[12];
    const float* Wgu      = (const float*)d_in[13];
    const float* Wd       = (const float*)d_in[14];
    float* out = (float*)d_out;

    static int s_attr_done = 0;
    if (!s_attr_done){
        cudaFuncSetAttribute(k_gemm1, cudaFuncAttributeMaxDynamicSharedMemorySize, SMEM_DYN);
        cudaFuncSetAttribute(k_gemm2, cudaFuncAttributeMaxDynamicSharedMemorySize, SMEM_DYN);
        s_attr_done = 1;
    }

    k_setup<<<1, 256>>>(topk_ids, topk_w, widx, seq_lens, ranks, scalings);
    k_lora_in<<<NPAIR, 256>>>(x, gate_a, up_a);
    k_gemm1<<<dim3(MAXT, NCT1), 256, SMEM_DYN>>>(Wgu, gate_b, up_b);
    k_act<<<4096, 256>>>();
    k_lora_mid<<<NPAIR, 256>>>(down_a);
    k_gemm2<<<dim3(MAXT, NCT2), 256, SMEM_DYN>>>(Wd, down_b);
    k_combine<<<NTOK, 256>>>(out);
}

// round 4
// speedup vs baseline: 2.7017x; 1.1169x over previous
#include <cuda_runtime.h>
#include <math.h>
#include <stdint.h>

// ---------------- problem constants ----------------
#define NTOK  2048
#define HID   1024
#define ITR   2816
#define NEXP  8
#define NADP  2
#define RNK   16
#define TOPK  2
#define NSEQ  8
#define NPAIR (NTOK*TOPK)        // 4096
#define NPAD  (NPAIR + 128)

// ---------------- GEMM tiling (mma.sync m16n8k8 tf32) ----------------
#define BM 128
#define BN 128
#define BKC 32                    // fp32 K elements per chunk (= 128B row)
#define TILEF (BM*32)             // 4096 floats per operand tile
#define STAGEF (2*TILEF)          // 8192 floats per stage (A+B)
#define SMEM_DYN (2*STAGEF*4)     // 65536 bytes (2 stages)
#define NK1 (HID/BKC)             // 32
#define NK2 (ITR/BKC)             // 88
#define MAXT (NPAIR/BM + NEXP)    // 40
#define NCT1 ((2*ITR)/BN)         // 44
#define NCT2 (HID/BN)             // 8

// ---------------- device scratch ----------------
__device__ int   g_tok[NPAIR];
__device__ float g_w[NPAIR];
__device__ int   g_ad[NPAIR];
__device__ float g_scale[NPAIR];
__device__ int   g_rank[NPAIR];
__device__ int   g_exp[NPAIR];
__device__ int   g_slot[NPAIR];
__device__ int   g2_ntiles;
__device__ int   g2_e[MAXT];
__device__ int   g2_m0[MAXT];
__device__ int   g2_rows[MAXT];
__device__ float g_zg[NPAIR*RNK];
__device__ float g_zu[NPAIR*RNK];
__device__ float g_zd[NPAIR*RNK];
__device__ float g_xg[(size_t)NPAD*HID];       // gathered x rows by slot
__device__ float g_act[(size_t)NPAD*ITR];      // silu(g)*u (fp32)
__device__ float g_gu[(size_t)NPAIR*2*ITR];    // gate|up outputs
__device__ float g_pout[(size_t)NPAIR*HID];    // per-pair weighted down out

// ---------------- helpers ----------------
__device__ __forceinline__ float f2tf(float x){
    uint32_t u;
    asm("cvt.rna.tf32.f32 %0, %1;" : "=r"(u) : "f"(x));
    return __uint_as_float(u);
}
__device__ __forceinline__ void mma8(float* c, const uint32_t* a, const uint32_t* b){
    asm volatile("mma.sync.aligned.m16n8k8.row.col.f32.tf32.tf32.f32 "
        "{%0,%1,%2,%3}, {%4,%5,%6,%7}, {%8,%9}, {%0,%1,%2,%3};"
        : "+f"(c[0]), "+f"(c[1]), "+f"(c[2]), "+f"(c[3])
        : "r"(a[0]), "r"(a[1]), "r"(a[2]), "r"(a[3]), "r"(b[0]), "r"(b[1]));
}
// swizzled float index of element (row, k) in a 128x32 tile
__device__ __forceinline__ int swz(int row, int k){
    return row*32 + 4*(((k >> 2) ^ row) & 7) + (k & 3);
}

// ---------------- mainloop: C[128x128] += A[128xK] * B[128xK]^T ----------------
__device__ __forceinline__ void gemm_core(const float* __restrict__ Ab, int lda,
                                          const float* __restrict__ Bb, int ldb,
                                          int nk, float* smf, float (*acc)[4][4])
{
    int tid = threadIdx.x, lane = tid & 31, wid = tid >> 5;
    int wm = wid & 1, wn = wid >> 1;
    int g = lane >> 2, tg = lane & 3;
    int rb = tid >> 3;                 // 0..31, store row base
    int c4 = tid & 7;                  // granule
    int sg = (c4 ^ (rb & 7)) * 4;      // swizzled store col offset (floats)

    float* Ast[2] = { smf, smf + STAGEF };
    float* Bst[2] = { smf + TILEF, smf + STAGEF + TILEF };
    float4 pa[4], pb[4];

    // prologue: load + fill stage 0
    #pragma unroll
    for (int q = 0; q < 4; q++){
        pa[q] = *(const float4*)(Ab + (size_t)(rb + 32*q)*lda + c4*4);
        pb[q] = *(const float4*)(Bb + (size_t)(rb + 32*q)*ldb + c4*4);
    }
    #pragma unroll
    for (int q = 0; q < 4; q++){
        float4 va = make_float4(f2tf(pa[q].x), f2tf(pa[q].y), f2tf(pa[q].z), f2tf(pa[q].w));
        float4 vb = make_float4(f2tf(pb[q].x), f2tf(pb[q].y), f2tf(pb[q].z), f2tf(pb[q].w));
        *(float4*)(Ast[0] + (rb + 32*q)*32 + sg) = va;
        *(float4*)(Bst[0] + (rb + 32*q)*32 + sg) = vb;
    }
    __syncthreads();

    for (int kc = 0; kc < nk; kc++){
        bool more = (kc + 1 < nk);
        if (more){
            int kof = (kc + 1)*BKC;
            #pragma unroll
            for (int q = 0; q < 4; q++){
                pa[q] = *(const float4*)(Ab + (size_t)(rb + 32*q)*lda + kof + c4*4);
                pb[q] = *(const float4*)(Bb + (size_t)(rb + 32*q)*ldb + kof + c4*4);
            }
        }
        const float* As = Ast[kc & 1];
        const float* Bs = Bst[kc & 1];
        #pragma unroll
        for (int ks = 0; ks < 4; ks++){
            int k0 = ks*8;
            uint32_t ar[4][4], br[4][2];
            #pragma unroll
            for (int mf = 0; mf < 4; mf++){
                int r0 = wm*64 + mf*16 + g;
                ar[mf][0] = __float_as_uint(As[swz(r0,     k0 + tg)]);
                ar[mf][1] = __float_as_uint(As[swz(r0 + 8, k0 + tg)]);
                ar[mf][2] = __float_as_uint(As[swz(r0,     k0 + tg + 4)]);
                ar[mf][3] = __float_as_uint(As[swz(r0 + 8, k0 + tg + 4)]);
            }
            #pragma unroll
            for (int nf = 0; nf < 4; nf++){
                int rB = wn*32 + nf*8 + g;
                br[nf][0] = __float_as_uint(Bs[swz(rB, k0 + tg)]);
                br[nf][1] = __float_as_uint(Bs[swz(rB, k0 + tg + 4)]);
            }
            #pragma unroll
            for (int mf = 0; mf < 4; mf++)
                #pragma unroll
                for (int nf = 0; nf < 4; nf++)
                    mma8(acc[mf][nf], ar[mf], br[nf]);
        }
        if (more){
            int s = (kc + 1) & 1;
            #pragma unroll
            for (int q = 0; q < 4; q++){
                float4 va = make_float4(f2tf(pa[q].x), f2tf(pa[q].y), f2tf(pa[q].z), f2tf(pa[q].w));
                float4 vb = make_float4(f2tf(pb[q].x), f2tf(pb[q].y), f2tf(pb[q].z), f2tf(pb[q].w));
                *(float4*)(Ast[s] + (rb + 32*q)*32 + sg) = va;
                *(float4*)(Bst[s] + (rb + 32*q)*32 + sg) = vb;
            }
        }
        __syncthreads();
    }
}

// ---------------- setup ----------------
__global__ void k_setup(const int* __restrict__ topk_ids, const float* __restrict__ topk_w,
                        const int* __restrict__ widx, const int* __restrict__ seq_lens,
                        const int* __restrict__ ranks, const float* __restrict__ scalings)
{
    __shared__ int cnt[NEXP*NADP], off[NEXP*NADP], cur[NEXP*NADP], cum[NSEQ];
    int tid = threadIdx.x;
    if (tid < NEXP*NADP) cnt[tid] = 0;
    __syncthreads();
    if (tid == 0){ int c = 0; for (int s = 0; s < NSEQ; s++){ c += seq_lens[s]; cum[s] = c; } }
    __syncthreads();
    for (int p = tid; p < NPAIR; p += blockDim.x){
        int n = p / TOPK; int e = topk_ids[p];
        int s = 0; while (n >= cum[s]) s++;
        atomicAdd(&cnt[e*NADP + widx[s]], 1);
    }
    __syncthreads();
    if (tid == 0){
        int acc = 0;
        for (int k = 0; k < NEXP*NADP; k++){ off[k] = acc; cur[k] = acc; acc += cnt[k]; }
        int nt = 0;
        for (int e = 0; e < NEXP; e++){
            int base = off[e*NADP];
            int c = cnt[e*NADP] + cnt[e*NADP+1];
            for (int r0 = 0; r0 < c; r0 += BM){
                g2_e[nt] = e; g2_m0[nt] = base + r0; g2_rows[nt] = min(BM, c - r0); nt++;
            }
        }
        g2_ntiles = nt;
    }
    __syncthreads();
    for (int p = tid; p < NPAIR; p += blockDim.x){
        int n = p / TOPK; int e = topk_ids[p];
        int s = 0; while (n >= cum[s]) s++;
        int a = widx[s];
        int slot = atomicAdd(&cur[e*NADP + a], 1);
        g_tok[slot] = n; g_w[slot] = topk_w[p]; g_ad[slot] = a;
        g_scale[slot] = scalings[a]; g_rank[slot] = ranks[a]; g_exp[slot] = e;
        g_slot[p] = slot;
    }
}

// ---------------- LoRA in-projection + gather x ----------------
__global__ void k_lora_in(const float* __restrict__ x,
                          const float* __restrict__ gate_a,
                          const float* __restrict__ up_a)
{
    int slot = blockIdx.x;
    int tok = g_tok[slot], a = g_ad[slot], e = g_exp[slot], rank = g_rank[slot];
    __shared__ float xs[HID];
    int tid = threadIdx.x;
    for (int i = tid; i < HID; i += blockDim.x){
        float v = x[(size_t)tok*HID + i];
        xs[i] = v;
        g_xg[(size_t)slot*HID + i] = v;
    }
    __syncthreads();
    int warp = tid >> 5, lane = tid & 31;
    for (int r = warp; r < RNK; r += 8){
        const float* ga = gate_a + ((size_t)((a*NEXP + e)*RNK) + r)*HID;
        const float* ua = up_a   + ((size_t)((a*NEXP + e)*RNK) + r)*HID;
        float a0 = 0.f, a1 = 0.f;
        for (int h = lane; h < HID; h += 32){ a0 += xs[h]*ga[h]; a1 += xs[h]*ua[h]; }
        #pragma unroll
        for (int o = 16; o; o >>= 1){
            a0 += __shfl_down_sync(0xffffffffu, a0, o);
            a1 += __shfl_down_sync(0xffffffffu, a1, o);
        }
        if (lane == 0){
            g_zg[slot*RNK + r] = (r < rank) ? a0 : 0.f;
            g_zu[slot*RNK + r] = (r < rank) ? a1 : 0.f;
        }
    }
}

// ---------------- GEMM1: g_gu = X @ Wgu^T + scale * z @ B^T ----------------
__global__ __launch_bounds__(256, 1) void k_gemm1(const float* __restrict__ Wgu,
                                                  const float* __restrict__ gb,
                                                  const float* __restrict__ ub)
{
    int t = blockIdx.x;
    if (t >= g2_ntiles) return;
    int e = g2_e[t], m0 = g2_m0[t], rows = g2_rows[t];
    int j0 = blockIdx.y * BN;
    bool isGate = (j0 < ITR);

    extern __shared__ float smf[];
    __shared__ float s_scale[BM];
    __shared__ int   s_ad[BM];

    float acc[4][4][4];
    #pragma unroll
    for (int i = 0; i < 4; i++)
        #pragma unroll
        for (int j = 0; j < 4; j++)
            #pragma unroll
            for (int k = 0; k < 4; k++) acc[i][j][k] = 0.f;

    const float* Ab = g_xg + (size_t)m0*HID;
    const float* Bb = Wgu + (size_t)e*(2*ITR)*HID + (size_t)j0*HID;
    gemm_core(Ab, HID, Bb, HID, NK1, smf, acc);

    // stage LoRA B rows + z into smem
    int tid = threadIdx.x, lane = tid & 31, wid = tid >> 5;
    float* blsm = smf;               // [2][128][16] = 4096 floats
    float* zsm  = smf + 4096;        // [128][16]    = 2048 floats
    const float* Bl = isGate ? gb : ub;
    int c0g = isGate ? j0 : (j0 - ITR);
    #pragma unroll
    for (int q = 0; q < 4; q++){
        int idx = tid + q*256;       // 0..1023
        int a = idx >> 9, rem = idx & 511, col = rem >> 2, f = rem & 3;
        *(float4*)(blsm + (size_t)idx*4) =
            *(const float4*)(Bl + ((size_t)(a*NEXP + e)*ITR + c0g + col)*RNK + f*4);
    }
    const float* zsrc = isGate ? g_zg : g_zu;
    #pragma unroll
    for (int q = 0; q < 2; q++){
        int idx = tid + q*256;       // 0..511
        int row = idx >> 2, f = idx & 3;
        int slot = m0 + row; if (slot >= NPAIR) slot = NPAIR - 1;
        *(float4*)(zsm + (size_t)idx*4) = *(const float4*)(zsrc + (size_t)slot*RNK + f*4);
    }
    if (tid < BM){
        int slot = min(m0 + tid, NPAIR - 1);
        s_scale[tid] = g_scale[slot]; s_ad[tid] = g_ad[slot];
    }
    __syncthreads();

    int wm = wid & 1, wn = wid >> 1, g = lane >> 2, tg = lane & 3;
    #pragma unroll
    for (int mf = 0; mf < 4; mf++){
        #pragma unroll
        for (int h = 0; h < 2; h++){
            int row = wm*64 + mf*16 + g + h*8;
            if (row >= rows) continue;
            float sc = s_scale[row]; int a = s_ad[row];
            const float* zr = zsm + row*16;
            float z[16];
            #pragma unroll
            for (int r = 0; r < 16; r += 4){
                float4 v = *(const float4*)(zr + r);
                z[r]=v.x; z[r+1]=v.y; z[r+2]=v.z; z[r+3]=v.w;
            }
            float* orow = g_gu + (size_t)(m0 + row)*(2*ITR) + j0;
            #pragma unroll
            for (int nf = 0; nf < 4; nf++){
                #pragma unroll
                for (int p = 0; p < 2; p++){
                    int cn = wn*32 + nf*8 + 2*tg + p;
                    const float* bl = blsm + (size_t)(a*BM + cn)*16;
                    float l = 0.f;
                    #pragma unroll
                    for (int r = 0; r < 16; r++) l += z[r]*bl[r];
                    orow[cn] = acc[mf][nf][h*2 + p] + sc*l;
                }
            }
        }
    }
}

// ---------------- act = silu(gate)*up (fp32) ----------------
__global__ void k_act()
{
    const size_t total = (size_t)NPAIR*(ITR/4);
    for (size_t idx = (size_t)blockIdx.x*blockDim.x + threadIdx.x; idx < total;
         idx += (size_t)gridDim.x*blockDim.x){
        size_t p = idx / (ITR/4);
        size_t i4 = idx % (ITR/4);
        const float4 g = *(const float4*)(g_gu + p*(2*ITR) + i4*4);
        const float4 u = *(const float4*)(g_gu + p*(2*ITR) + ITR + i4*4);
        float4 o;
        o.x = g.x/(1.f + expf(-g.x)) * u.x;
        o.y = g.y/(1.f + expf(-g.y)) * u.y;
        o.z = g.z/(1.f + expf(-g.z)) * u.z;
        o.w = g.w/(1.f + expf(-g.w)) * u.w;
        *(float4*)(g_act + p*ITR + i4*4) = o;
    }
}

// ---------------- LoRA mid-projection zd ----------------
__global__ void k_lora_mid(const float* __restrict__ down_a)
{
    int slot = blockIdx.x;
    int a = g_ad[slot], e = g_exp[slot], rank = g_rank[slot];
    __shared__ float as[ITR];
    int tid = threadIdx.x;
    for (int i = tid; i < ITR; i += blockDim.x) as[i] = g_act[(size_t)slot*ITR + i];
    __syncthreads();
    int warp = tid >> 5, lane = tid & 31;
    for (int r = warp; r < RNK; r += 8){
        const float* da = down_a + ((size_t)((a*NEXP + e)*RNK) + r)*ITR;
        float acc = 0.f;
        for (int i = lane; i < ITR; i += 32) acc += as[i]*da[i];
        #pragma unroll
        for (int o = 16; o; o >>= 1) acc += __shfl_down_sync(0xffffffffu, acc, o);
        if (lane == 0) g_zd[slot*RNK + r] = (r < rank) ? acc : 0.f;
    }
}

// ---------------- GEMM2: pout = w*(act @ Wd^T + scale * zd @ db^T) ----------------
__global__ __launch_bounds__(256, 1) void k_gemm2(const float* __restrict__ Wd,
                                                  const float* __restrict__ db)
{
    int t = blockIdx.x;
    if (t >= g2_ntiles) return;
    int e = g2_e[t], m0 = g2_m0[t], rows = g2_rows[t];
    int j0 = blockIdx.y * BN;

    extern __shared__ float smf[];
    __shared__ float s_scale[BM];
    __shared__ float s_wt[BM];
    __shared__ int   s_ad[BM];

    float acc[4][4][4];
    #pragma unroll
    for (int i = 0; i < 4; i++)
        #pragma unroll
        for (int j = 0; j < 4; j++)
            #pragma unroll
            for (int k = 0; k < 4; k++) acc[i][j][k] = 0.f;

    const float* Ab = g_act + (size_t)m0*ITR;
    const float* Bb = Wd + (size_t)e*HID*ITR + (size_t)j0*ITR;
    gemm_core(Ab, ITR, Bb, ITR, NK2, smf, acc);

    int tid = threadIdx.x, lane = tid & 31, wid = tid >> 5;
    float* blsm = smf;
    float* zsm  = smf + 4096;
    #pragma unroll
    for (int q = 0; q < 4; q++){
        int idx = tid + q*256;
        int a = idx >> 9, rem = idx & 511, col = rem >> 2, f = rem & 3;
        *(float4*)(blsm + (size_t)idx*4) =
            *(const float4*)(db + ((size_t)(a*NEXP + e)*HID + j0 + col)*RNK + f*4);
    }
    #pragma unroll
    for (int q = 0; q < 2; q++){
        int idx = tid + q*256;
        int row = idx >> 2, f = idx & 3;
        int slot = m0 + row; if (slot >= NPAIR) slot = NPAIR - 1;
        *(float4*)(zsm + (size_t)idx*4) = *(const float4*)(g_zd + (size_t)slot*RNK + f*4);
    }
    if (tid < BM){
        int slot = min(m0 + tid, NPAIR - 1);
        s_scale[tid] = g_scale[slot]; s_ad[tid] = g_ad[slot]; s_wt[tid] = g_w[slot];
    }
    __syncthreads();

    int wm = wid & 1, wn = wid >> 1, g = lane >> 2, tg = lane & 3;
    #pragma unroll
    for (int mf = 0; mf < 4; mf++){
        #pragma unroll
        for (int h = 0; h < 2; h++){
            int row = wm*64 + mf*16 + g + h*8;
            if (row >= rows) continue;
            float sc = s_scale[row]; float w = s_wt[row]; int a = s_ad[row];
            const float* zr = zsm + row*16;
            float z[16];
            #pragma unroll
            for (int r = 0; r < 16; r += 4){
                float4 v = *(const float4*)(zr + r);
                z[r]=v.x; z[r+1]=v.y; z[r+2]=v.z; z[r+3]=v.w;
            }
            float* orow = g_pout + (size_t)(m0 + row)*HID + j0;
            #pragma unroll
            for (int nf = 0; nf < 4; nf++){
                #pragma unroll
                for (int p = 0; p < 2; p++){
                    int cn = wn*32 + nf*8 + 2*tg + p;
                    const float* bl = blsm + (size_t)(a*BM + cn)*16;
                    float l = 0.f;
                    #pragma unroll
                    for (int r = 0; r < 16; r++) l += z[r]*bl[r];
                    orow[cn] = w * (acc[mf][nf][h*2 + p] + sc*l);
                }
            }
        }
    }
}

// ---------------- combine ----------------
__global__ void k_combine(float* __restrict__ out)
{
    int n = blockIdx.x;
    int s0 = g_slot[n*TOPK + 0];
    int s1 = g_slot[n*TOPK + 1];
    int tid = threadIdx.x;   // HID/4 == 256
    const float4 a = ((const float4*)(g_pout + (size_t)s0*HID))[tid];
    const float4 b = ((const float4*)(g_pout + (size_t)s1*HID))[tid];
    ((float4*)(out + (size_t)n*HID))[tid] = make_float4(a.x+b.x, a.y+b.y, a.z+b.z, a.w+b.w);
}

// ---------------- launch ----------------
extern "C" void kernel_launch(void* const* d_in, const int* in_sizes, int n_in,
                              void* d_out, int out_size)
{
    const float* x        = (const float*)d_in[0];
    const int*   topk_ids = (const int*)  d_in[1];
    const float* topk_w   = (const float*)d_in[2];
    const float* gate_a   = (const float*)d_in[3];
    const float* gate_b   = (const float*)d_in[4];
    const float* up_a     = (const float*)d_in[5];
    const float* up_b     = (const float*)d_in[6];
    const float* down_a   = (const float*)d_in[7];
    const float* down_b   = (const float*)d_in[8];
    const int*   widx     = (const int*)  d_in[9];
    const int*   seq_lens = (const int*)  d_in[10];
    const int*   ranks    = (const int*)  d_in[11];
    const float* scalings = (const float*)d_in[12];
    const float* Wgu      = (const float*)d_in[13];
    const float* Wd       = (const float*)d_in[14];
    float* out = (float*)d_out;

    static int s_attr_done = 0;
    if (!s_attr_done){
        cudaFuncSetAttribute(k_gemm1, cudaFuncAttributeMaxDynamicSharedMemorySize, SMEM_DYN);
        cudaFuncSetAttribute(k_gemm2, cudaFuncAttributeMaxDynamicSharedMemorySize, SMEM_DYN);
        s_attr_done = 1;
    }

    k_setup<<<1, 256>>>(topk_ids, topk_w, widx, seq_lens, ranks, scalings);
    k_lora_in<<<NPAIR, 256>>>(x, gate_a, up_a);
    k_gemm1<<<dim3(MAXT, NCT1), 256, SMEM_DYN>>>(Wgu, gate_b, up_b);
    k_act<<<4096, 256>>>();
    k_lora_mid<<<NPAIR, 256>>>(down_a);
    k_gemm2<<<dim3(MAXT, NCT2), 256, SMEM_DYN>>>(Wd, down_b);
    k_combine<<<NTOK, 256>>>(out);
}

// round 5
// speedup vs baseline: 7.4281x; 2.7494x over previous
#include <cuda_runtime.h>
#include <cuda_fp16.h>
#include <math.h>
#include <stdint.h>

// ---------------- problem constants ----------------
#define NTOK  2048
#define HID   1024
#define ITR   2816
#define NEXP  8
#define NADP  2
#define RNK   16
#define TOPK  2
#define NSEQ  8
#define NPAIR (NTOK*TOPK)        // 4096
#define NPAD  (NPAIR + 128)

// ---------------- GEMM tiling (mma.sync m16n8k16 fp16) ----------------
#define BM 128
#define BN 128
#define BKH 64                    // half elements per k-chunk (=128B row, SW128)
#define STAGEB 32768              // A tile 16KB + B tile 16KB
#define SMEM_DYN (2*STAGEB)       // 65536
#define NK1 17                    // 1024/64 = 16 real + 1 lora-ext
#define NK2 45                    // 2816/64 = 44 real + 1 lora-ext
#define MAXT (NPAIR/BM + NEXP)    // 40
#define NCT1 (ITR/64)             // 44 (64 j-cols per CTA, gate+up interleaved)
#define NCT2 (HID/BN)             // 8

// ---------------- device scratch ----------------
__device__ int   g_tok[NPAIR];
__device__ float g_w[NPAIR];
__device__ int   g_ad[NPAIR];
__device__ float g_scale[NPAIR];
__device__ int   g_rank[NPAIR];
__device__ int   g_exp[NPAIR];
__device__ int   g_slot[NPAIR];
__device__ int   g2_ntiles;
__device__ int   g2_e[MAXT];
__device__ int   g2_m0[MAXT];
__device__ int   g2_rows[MAXT];
__device__ __align__(16) __half g_xg_h[(size_t)NPAD*HID];
__device__ __align__(16) __half g_act_h[(size_t)NPAD*ITR];
__device__ __align__(16) __half g_zgu_h[(size_t)NPAD*64];
__device__ __align__(16) __half g_zd_h[(size_t)NPAD*64];
__device__ __align__(16) __half g_wgu_h[(size_t)NEXP*2*ITR*HID];
__device__ __align__(16) __half g_wd_h[(size_t)NEXP*HID*ITR];
__device__ __align__(16) __half g_bg_ext[(size_t)NEXP*2*ITR*64];
__device__ __align__(16) __half g_bd_ext[(size_t)NEXP*HID*64];
__device__ float g_pout[(size_t)NPAIR*HID];

// ---------------- PTX helpers ----------------
__device__ __forceinline__ uint32_t s2u(const void* p){
    uint32_t a;
    asm("{ .reg .u64 t; cvta.to.shared.u64 t, %1; cvt.u32.u64 %0, t; }":"=r"(a):"l"(p));
    return a;
}
__device__ __forceinline__ void cpa16(uint32_t dst, const void* src){
    asm volatile("cp.async.cg.shared.global [%0], [%1], 16;" :: "r"(dst), "l"(src));
}
__device__ __forceinline__ void cp_commit(){ asm volatile("cp.async.commit_group;":::"memory"); }
__device__ __forceinline__ void cp_wait1(){ asm volatile("cp.async.wait_group 1;":::"memory"); }
__device__ __forceinline__ void cp_wait0(){ asm volatile("cp.async.wait_group 0;":::"memory"); }
__device__ __forceinline__ void ldsm4(uint32_t* r, uint32_t addr){
    asm volatile("ldmatrix.sync.aligned.m8n8.x4.shared.b16 {%0,%1,%2,%3}, [%4];"
      : "=r"(r[0]),"=r"(r[1]),"=r"(r[2]),"=r"(r[3]) : "r"(addr));
}
__device__ __forceinline__ void mma16(float* c, const uint32_t* a, const uint32_t* b){
    asm volatile("mma.sync.aligned.m16n8k16.row.col.f32.f16.f16.f32 "
      "{%0,%1,%2,%3},{%4,%5,%6,%7},{%8,%9},{%0,%1,%2,%3};"
      : "+f"(c[0]),"+f"(c[1]),"+f"(c[2]),"+f"(c[3])
      : "r"(a[0]),"r"(a[1]),"r"(a[2]),"r"(a[3]),"r"(b[0]),"r"(b[1]));
}

// ---------------- shared mainloop compute: one 64-wide k-chunk ----------------
__device__ __forceinline__ void stage_mma(uint32_t smA, uint32_t smB,
                                          int lane, int wm, int wn,
                                          float (*acc)[4][4])
{
    int ra = (lane & 7) + (((lane >> 3) & 1) << 3);  // A row-in-16
    int ka = lane >> 4;                               // A granule off
    int rb = (lane & 7) + ((lane >> 4) << 3);         // B row-in-16
    int kb = (lane >> 3) & 1;                         // B granule off
    #pragma unroll
    for (int ks = 0; ks < 4; ks++){
        uint32_t a[4][4], b[2][4];
        #pragma unroll
        for (int mf = 0; mf < 4; mf++){
            int row = wm*64 + mf*16 + ra;
            int kgr = ks*2 + ka;
            ldsm4(a[mf], smA + row*128 + ((kgr ^ (row & 7)) << 4));
        }
        #pragma unroll
        for (int nfp = 0; nfp < 2; nfp++){
            int row = wn*32 + nfp*16 + rb;
            int kgr = ks*2 + kb;
            ldsm4(b[nfp], smB + row*128 + ((kgr ^ (row & 7)) << 4));
        }
        #pragma unroll
        for (int mf = 0; mf < 4; mf++){
            mma16(acc[mf][0], a[mf], b[0] + 0);
            mma16(acc[mf][1], a[mf], b[0] + 2);
            mma16(acc[mf][2], a[mf], b[1] + 0);
            mma16(acc[mf][3], a[mf], b[1] + 2);
        }
    }
}

// ---------------- setup ----------------
__global__ void k_setup(const int* __restrict__ topk_ids, const float* __restrict__ topk_w,
                        const int* __restrict__ widx, const int* __restrict__ seq_lens,
                        const int* __restrict__ ranks, const float* __restrict__ scalings)
{
    __shared__ int cnt[NEXP*NADP], off[NEXP*NADP], cur[NEXP*NADP], cum[NSEQ];
    int tid = threadIdx.x;
    if (tid < NEXP*NADP) cnt[tid] = 0;
    __syncthreads();
    if (tid == 0){ int c = 0; for (int s = 0; s < NSEQ; s++){ c += seq_lens[s]; cum[s] = c; } }
    __syncthreads();
    for (int p = tid; p < NPAIR; p += blockDim.x){
        int n = p / TOPK; int e = topk_ids[p];
        int s = 0; while (n >= cum[s]) s++;
        atomicAdd(&cnt[e*NADP + widx[s]], 1);
    }
    __syncthreads();
    if (tid == 0){
        int acc = 0;
        for (int k = 0; k < NEXP*NADP; k++){ off[k] = acc; cur[k] = acc; acc += cnt[k]; }
        int nt = 0;
        for (int e = 0; e < NEXP; e++){
            int base = off[e*NADP];
            int c = cnt[e*NADP] + cnt[e*NADP+1];
            for (int r0 = 0; r0 < c; r0 += BM){
                g2_e[nt] = e; g2_m0[nt] = base + r0; g2_rows[nt] = min(BM, c - r0); nt++;
            }
        }
        g2_ntiles = nt;
    }
    __syncthreads();
    for (int p = tid; p < NPAIR; p += blockDim.x){
        int n = p / TOPK; int e = topk_ids[p];
        int s = 0; while (n >= cum[s]) s++;
        int a = widx[s];
        int slot = atomicAdd(&cur[e*NADP + a], 1);
        g_tok[slot] = n; g_w[slot] = topk_w[p]; g_ad[slot] = a;
        g_scale[slot] = scalings[a]; g_rank[slot] = ranks[a]; g_exp[slot] = e;
        g_slot[p] = slot;
    }
}

// ---------------- weight conversions fp32 -> fp16 ----------------
__global__ void k_convw(const float* __restrict__ wgu, const float* __restrict__ wd)
{
    const size_t n1 = (size_t)NEXP*2*ITR*HID/4;
    const size_t n2 = (size_t)NEXP*HID*ITR/4;
    size_t stride = (size_t)gridDim.x*blockDim.x;
    __half2* o1 = (__half2*)g_wgu_h;
    __half2* o2 = (__half2*)g_wd_h;
    for (size_t i = (size_t)blockIdx.x*blockDim.x + threadIdx.x; i < n1; i += stride){
        float4 v = ((const float4*)wgu)[i];
        o1[2*i]   = __float22half2_rn(make_float2(v.x, v.y));
        o1[2*i+1] = __float22half2_rn(make_float2(v.z, v.w));
    }
    for (size_t i = (size_t)blockIdx.x*blockDim.x + threadIdx.x; i < n2; i += stride){
        float4 v = ((const float4*)wd)[i];
        o2[2*i]   = __float22half2_rn(make_float2(v.x, v.y));
        o2[2*i+1] = __float22half2_rn(make_float2(v.z, v.w));
    }
}

// ---------------- build LoRA-B K-extension tiles ----------------
__global__ void k_prep_ext(const float* __restrict__ gb, const float* __restrict__ ub,
                           const float* __restrict__ db)
{
    size_t stride = (size_t)gridDim.x*blockDim.x;
    const size_t n1 = (size_t)NEXP*2*ITR*64;
    for (size_t i = (size_t)blockIdx.x*blockDim.x + threadIdx.x; i < n1; i += stride){
        int c = (int)(i & 63);
        size_t R = (i >> 6);
        int e = (int)(R / (2*ITR));
        int r = (int)(R % (2*ITR));
        int j = r >> 1;
        float v = 0.f;
        if (!(r & 1)){
            if (c < 16) v = gb[((size_t)(0*NEXP + e)*ITR + j)*RNK + c];
            else if (c >= 32 && c < 48) v = gb[((size_t)(1*NEXP + e)*ITR + j)*RNK + (c - 32)];
        } else {
            if (c >= 16 && c < 32) v = ub[((size_t)(0*NEXP + e)*ITR + j)*RNK + (c - 16)];
            else if (c >= 48) v = ub[((size_t)(1*NEXP + e)*ITR + j)*RNK + (c - 48)];
        }
        g_bg_ext[i] = __float2half(v);
    }
    const size_t n2 = (size_t)NEXP*HID*64;
    for (size_t i = (size_t)blockIdx.x*blockDim.x + threadIdx.x; i < n2; i += stride){
        int c = (int)(i & 63);
        size_t R = (i >> 6);
        int e = (int)(R / HID);
        int h = (int)(R % HID);
        float v = 0.f;
        if (c < 16) v = db[((size_t)(0*NEXP + e)*HID + h)*RNK + c];
        else if (c < 32) v = db[((size_t)(1*NEXP + e)*HID + h)*RNK + (c - 16)];
        g_bd_ext[i] = __float2half(v);
    }
}

// ---------------- LoRA in-projection + x gather (half) + A-ext ----------------
__global__ void k_lora_in(const float* __restrict__ x,
                          const float* __restrict__ gate_a,
                          const float* __restrict__ up_a)
{
    int slot = blockIdx.x;
    int tok = g_tok[slot], a = g_ad[slot], e = g_exp[slot], rank = g_rank[slot];
    float sc = g_scale[slot];
    __shared__ float xs[HID];
    __shared__ float zz[32];
    int tid = threadIdx.x;
    {   // exactly one float4 per thread (HID/4 == 256)
        float4 v = ((const float4*)(x + (size_t)tok*HID))[tid];
        ((float4*)xs)[tid] = v;
        __half2* xh = (__half2*)(g_xg_h + (size_t)slot*HID);
        xh[2*tid]   = __float22half2_rn(make_float2(v.x, v.y));
        xh[2*tid+1] = __float22half2_rn(make_float2(v.z, v.w));
    }
    __syncthreads();
    int warp = tid >> 5, lane = tid & 31;
    for (int r = warp; r < RNK; r += 8){
        const float* ga = gate_a + ((size_t)((a*NEXP + e)*RNK) + r)*HID;
        const float* ua = up_a   + ((size_t)((a*NEXP + e)*RNK) + r)*HID;
        float a0 = 0.f, a1 = 0.f;
        for (int h = lane; h < HID; h += 32){ a0 += xs[h]*ga[h]; a1 += xs[h]*ua[h]; }
        #pragma unroll
        for (int o = 16; o; o >>= 1){
            a0 += __shfl_down_sync(0xffffffffu, a0, o);
            a1 += __shfl_down_sync(0xffffffffu, a1, o);
        }
        if (lane == 0){
            zz[r]      = (r < rank) ? a0 : 0.f;
            zz[16 + r] = (r < rank) ? a1 : 0.f;
        }
    }
    __syncthreads();
    if (tid < 64){
        float v = 0.f;
        if (a == 0){ if (tid < 32) v = sc*zz[tid]; }
        else       { if (tid >= 32) v = sc*zz[tid - 32]; }
        g_zgu_h[(size_t)slot*64 + tid] = __float2half(v);
    }
}

// ---------------- GEMM1 fill (one k-chunk into stage s) ----------------
__device__ __forceinline__ void fill1(uint32_t smb, int s, int kc, int tid,
                                      int e, int m0, int j064)
{
    uint32_t ab = smb + s*STAGEB;
    uint32_t bb = ab + 16384;
    #pragma unroll
    for (int q = 0; q < 4; q++){
        int G = tid + 256*q; int row = G >> 3, gr = G & 7;
        uint32_t off = row*128 + ((gr ^ (row & 7)) << 4);
        const __half* sa = (kc < 16)
            ? g_xg_h + (size_t)(m0 + row)*HID + kc*64 + gr*8
            : g_zgu_h + (size_t)(m0 + row)*64 + gr*8;
        cpa16(ab + off, sa);
        const __half* sb;
        if (kc < 16){
            int sr = ((row & 1) ? ITR : 0) + j064 + (row >> 1);
            sb = g_wgu_h + ((size_t)e*(2*ITR) + sr)*HID + kc*64 + gr*8;
        } else {
            sb = g_bg_ext + ((size_t)e*(2*ITR) + 2*j064 + row)*64 + gr*8;
        }
        cpa16(bb + off, sb);
    }
}

// ---------------- GEMM1: fused gate/up + LoRA + SiLU -> g_act_h ----------------
__global__ __launch_bounds__(256, 2) void k_gemm1()
{
    int t = blockIdx.x;
    if (t >= g2_ntiles) return;
    int e = g2_e[t], m0 = g2_m0[t], rows = g2_rows[t];
    int j064 = blockIdx.y * 64;

    extern __shared__ char smc[];
    uint32_t smb = s2u(smc);
    int tid = threadIdx.x, lane = tid & 31, wid = tid >> 5;
    int wm = wid & 1, wn = wid >> 1;

    float acc[4][4][4];
    #pragma unroll
    for (int i = 0; i < 4; i++)
        #pragma unroll
        for (int j = 0; j < 4; j++)
            #pragma unroll
            for (int k = 0; k < 4; k++) acc[i][j][k] = 0.f;

    fill1(smb, 0, 0, tid, e, m0, j064); cp_commit();
    for (int kc = 0; kc < NK1; kc++){
        if (kc + 1 < NK1){
            fill1(smb, (kc + 1) & 1, kc + 1, tid, e, m0, j064); cp_commit(); cp_wait1();
        } else cp_wait0();
        __syncthreads();
        uint32_t st = smb + (kc & 1)*STAGEB;
        stage_mma(st, st + 16384, lane, wm, wn, acc);
        __syncthreads();
    }

    int g = lane >> 2, tg = lane & 3;
    #pragma unroll
    for (int mf = 0; mf < 4; mf++){
        #pragma unroll
        for (int h = 0; h < 2; h++){
            int row = wm*64 + mf*16 + g + h*8;
            if (row >= rows) continue;
            __half* arow = g_act_h + (size_t)(m0 + row)*ITR + j064;
            #pragma unroll
            for (int nf = 0; nf < 4; nf++){
                float gate = acc[mf][nf][h*2 + 0];
                float up   = acc[mf][nf][h*2 + 1];
                float act = gate / (1.f + __expf(-gate)) * up;
                arow[wn*16 + nf*4 + tg] = __float2half(act);
            }
        }
    }
}

// ---------------- LoRA mid-projection zd + A-ext ----------------
__global__ void k_lora_mid(const float* __restrict__ down_a)
{
    int slot = blockIdx.x;
    int a = g_ad[slot], e = g_exp[slot], rank = g_rank[slot];
    float sc = g_scale[slot];
    __shared__ float as[ITR];
    __shared__ float zz[16];
    int tid = threadIdx.x;
    for (int i = tid; i < ITR/8; i += 256){
        uint4 raw = ((const uint4*)(g_act_h + (size_t)slot*ITR))[i];
        const __half2* hp = (const __half2*)&raw;
        #pragma unroll
        for (int k = 0; k < 4; k++){
            float2 f = __half22float2(hp[k]);
            as[i*8 + 2*k]     = f.x;
            as[i*8 + 2*k + 1] = f.y;
        }
    }
    __syncthreads();
    int warp = tid >> 5, lane = tid & 31;
    for (int r = warp; r < RNK; r += 8){
        const float* da = down_a + ((size_t)((a*NEXP + e)*RNK) + r)*ITR;
        float acc = 0.f;
        for (int i = lane; i < ITR; i += 32) acc += as[i]*da[i];
        #pragma unroll
        for (int o = 16; o; o >>= 1) acc += __shfl_down_sync(0xffffffffu, acc, o);
        if (lane == 0) zz[r] = (r < rank) ? acc : 0.f;
    }
    __syncthreads();
    if (tid < 64){
        float v = 0.f;
        if (tid < 16){ if (a == 0) v = sc*zz[tid]; }
        else if (tid < 32){ if (a == 1) v = sc*zz[tid - 16]; }
        g_zd_h[(size_t)slot*64 + tid] = __float2half(v);
    }
}

// ---------------- GEMM2 fill ----------------
__device__ __forceinline__ void fill2(uint32_t smb, int s, int kc, int tid,
                                      int e, int m0, int j0)
{
    uint32_t ab = smb + s*STAGEB;
    uint32_t bb = ab + 16384;
    #pragma unroll
    for (int q = 0; q < 4; q++){
        int G = tid + 256*q; int row = G >> 3, gr = G & 7;
        uint32_t off = row*128 + ((gr ^ (row & 7)) << 4);
        const __half* sa = (kc < 44)
            ? g_act_h + (size_t)(m0 + row)*ITR + kc*64 + gr*8
            : g_zd_h + (size_t)(m0 + row)*64 + gr*8;
        cpa16(ab + off, sa);
        const __half* sb = (kc < 44)
            ? g_wd_h + ((size_t)e*HID + j0 + row)*ITR + kc*64 + gr*8
            : g_bd_ext + ((size_t)e*HID + j0 + row)*64 + gr*8;
        cpa16(bb + off, sb);
    }
}

// ---------------- GEMM2: down proj + LoRA, weighted -> g_pout ----------------
__global__ __launch_bounds__(256, 2) void k_gemm2()
{
    int t = blockIdx.x;
    if (t >= g2_ntiles) return;
    int e = g2_e[t], m0 = g2_m0[t], rows = g2_rows[t];
    int j0 = blockIdx.y * BN;

    extern __shared__ char smc[];
    uint32_t smb = s2u(smc);
    __shared__ float s_wt[BM];
    int tid = threadIdx.x, lane = tid & 31, wid = tid >> 5;
    int wm = wid & 1, wn = wid >> 1;
    if (tid < BM) s_wt[tid] = g_w[min(m0 + tid, NPAIR - 1)];

    float acc[4][4][4];
    #pragma unroll
    for (int i = 0; i < 4; i++)
        #pragma unroll
        for (int j = 0; j < 4; j++)
            #pragma unroll
            for (int k = 0; k < 4; k++) acc[i][j][k] = 0.f;

    fill2(smb, 0, 0, tid, e, m0, j0); cp_commit();
    for (int kc = 0; kc < NK2; kc++){
        if (kc + 1 < NK2){
            fill2(smb, (kc + 1) & 1, kc + 1, tid, e, m0, j0); cp_commit(); cp_wait1();
        } else cp_wait0();
        __syncthreads();
        uint32_t st = smb + (kc & 1)*STAGEB;
        stage_mma(st, st + 16384, lane, wm, wn, acc);
        __syncthreads();
    }

    int g = lane >> 2, tg = lane & 3;
    #pragma unroll
    for (int mf = 0; mf < 4; mf++){
        #pragma unroll
        for (int h = 0; h < 2; h++){
            int row = wm*64 + mf*16 + g + h*8;
            if (row >= rows) continue;
            float w = s_wt[row];
            float* orow = g_pout + (size_t)(m0 + row)*HID + j0;
            #pragma unroll
            for (int nf = 0; nf < 4; nf++){
                int c = wn*32 + nf*8 + 2*tg;
                orow[c]     = w * acc[mf][nf][h*2 + 0];
                orow[c + 1] = w * acc[mf][nf][h*2 + 1];
            }
        }
    }
}

// ---------------- combine ----------------
__global__ void k_combine(float* __restrict__ out)
{
    int n = blockIdx.x;
    int s0 = g_slot[n*TOPK + 0];
    int s1 = g_slot[n*TOPK + 1];
    int tid = threadIdx.x;   // HID/4 == 256
    const float4 a = ((const float4*)(g_pout + (size_t)s0*HID))[tid];
    const float4 b = ((const float4*)(g_pout + (size_t)s1*HID))[tid];
    ((float4*)(out + (size_t)n*HID))[tid] = make_float4(a.x+b.x, a.y+b.y, a.z+b.z, a.w+b.w);
}

// ---------------- launch ----------------
extern "C" void kernel_launch(void* const* d_in, const int* in_sizes, int n_in,
                              void* d_out, int out_size)
{
    const float* x        = (const float*)d_in[0];
    const int*   topk_ids = (const int*)  d_in[1];
    const float* topk_w   = (const float*)d_in[2];
    const float* gate_a   = (const float*)d_in[3];
    const float* gate_b   = (const float*)d_in[4];
    const float* up_a     = (const float*)d_in[5];
    const float* up_b     = (const float*)d_in[6];
    const float* down_a   = (const float*)d_in[7];
    const float* down_b   = (const float*)d_in[8];
    const int*   widx     = (const int*)  d_in[9];
    const int*   seq_lens = (const int*)  d_in[10];
    const int*   ranks    = (const int*)  d_in[11];
    const float* scalings = (const float*)d_in[12];
    const float* Wgu      = (const float*)d_in[13];
    const float* Wd       = (const float*)d_in[14];
    float* out = (float*)d_out;

    static int s_attr_done = 0;
    if (!s_attr_done){
        cudaFuncSetAttribute(k_gemm1, cudaFuncAttributeMaxDynamicSharedMemorySize, SMEM_DYN);
        cudaFuncSetAttribute(k_gemm2, cudaFuncAttributeMaxDynamicSharedMemorySize, SMEM_DYN);
        s_attr_done = 1;
    }

    k_setup<<<1, 256>>>(topk_ids, topk_w, widx, seq_lens, ranks, scalings);
    k_convw<<<8192, 256>>>(Wgu, Wd);
    k_prep_ext<<<2048, 256>>>(gate_b, up_b, down_b);
    k_lora_in<<<NPAIR, 256>>>(x, gate_a, up_a);
    k_gemm1<<<dim3(MAXT, NCT1), 256, SMEM_DYN>>>();
    k_lora_mid<<<NPAIR, 256>>>(down_a);
    k_gemm2<<<dim3(MAXT, NCT2), 256, SMEM_DYN>>>();
    k_combine<<<NTOK, 256>>>(out);
}

// round 6
// speedup vs baseline: 8.5560x; 1.1518x over previous
#include <cuda_runtime.h>
#include <cuda_fp16.h>
#include <math.h>
#include <stdint.h>

// ---------------- problem constants ----------------
#define NTOK  2048
#define HID   1024
#define ITR   2816
#define NEXP  8
#define NADP  2
#define RNK   16
#define TOPK  2
#define NSEQ  8
#define NPAIR (NTOK*TOPK)        // 4096
#define NPAD  (NPAIR + 128)

// ---------------- GEMM tiling (mma.sync m16n8k16 fp16) ----------------
#define BM 128
#define BN 128
#define STAGEB 32768              // A tile 16KB + B tile 16KB
#define SMEM_DYN (2*STAGEB)       // 65536
#define NK1 17                    // 16 real + 1 lora-ext
#define NK2 45                    // 44 real + 1 lora-ext
#define MAXT (NPAIR/BM + NEXP)    // 40
#define NCT1 (ITR/64)             // 44
#define NCT2 (HID/BN)             // 8
// lora-A GEMM (N=64)
#define LSTAGE 24576              // A 16KB + B 8KB
#define LSMEM (2*LSTAGE)          // 49152

// ---------------- device scratch ----------------
__device__ int   g_tok[NPAIR];
__device__ float g_w[NPAIR];
__device__ int   g_ad[NPAIR];
__device__ float g_scale[NPAIR];
__device__ int   g_exp[NPAIR];
__device__ int   g2_ntiles;
__device__ int   g2_e[MAXT];
__device__ int   g2_m0[MAXT];
__device__ int   g2_rows[MAXT];
__device__ __align__(16) __half g_xg_h[(size_t)NPAD*HID];
__device__ __align__(16) __half g_act_h[(size_t)NPAD*ITR];
__device__ __align__(16) __half g_zgu_h[(size_t)NPAD*64];
__device__ __align__(16) __half g_zd_h[(size_t)NPAD*64];
__device__ __align__(16) __half g_wgu_h[(size_t)NEXP*2*ITR*HID];
__device__ __align__(16) __half g_wd_h[(size_t)NEXP*HID*ITR];
__device__ __align__(16) __half g_bg_ext[(size_t)NEXP*2*ITR*64];
__device__ __align__(16) __half g_bd_ext[(size_t)NEXP*HID*64];
__device__ __align__(16) __half g_a1h[(size_t)NEXP*64*HID];   // [e][ga0|ua0|ga1|ua1][HID]
__device__ __align__(16) __half g_a2h[(size_t)NEXP*64*ITR];   // [e][da0|da1|zeros][ITR]

// ---------------- PTX helpers ----------------
__device__ __forceinline__ uint32_t s2u(const void* p){
    uint32_t a;
    asm("{ .reg .u64 t; cvta.to.shared.u64 t, %1; cvt.u32.u64 %0, t; }":"=r"(a):"l"(p));
    return a;
}
__device__ __forceinline__ void cpa16(uint32_t dst, const void* src){
    asm volatile("cp.async.cg.shared.global [%0], [%1], 16;" :: "r"(dst), "l"(src));
}
__device__ __forceinline__ void cp_commit(){ asm volatile("cp.async.commit_group;":::"memory"); }
__device__ __forceinline__ void cp_wait1(){ asm volatile("cp.async.wait_group 1;":::"memory"); }
__device__ __forceinline__ void cp_wait0(){ asm volatile("cp.async.wait_group 0;":::"memory"); }
__device__ __forceinline__ void ldsm4(uint32_t* r, uint32_t addr){
    asm volatile("ldmatrix.sync.aligned.m8n8.x4.shared.b16 {%0,%1,%2,%3}, [%4];"
      : "=r"(r[0]),"=r"(r[1]),"=r"(r[2]),"=r"(r[3]) : "r"(addr));
}
__device__ __forceinline__ void mma16(float* c, const uint32_t* a, const uint32_t* b){
    asm volatile("mma.sync.aligned.m16n8k16.row.col.f32.f16.f16.f32 "
      "{%0,%1,%2,%3},{%4,%5,%6,%7},{%8,%9},{%0,%1,%2,%3};"
      : "+f"(c[0]),"+f"(c[1]),"+f"(c[2]),"+f"(c[3])
      : "r"(a[0]),"r"(a[1]),"r"(a[2]),"r"(a[3]),"r"(b[0]),"r"(b[1]));
}

// ---------------- BN=128 mainloop compute ----------------
__device__ __forceinline__ void stage_mma(uint32_t smA, uint32_t smB,
                                          int lane, int wm, int wn,
                                          float (*acc)[4][4])
{
    int ra = (lane & 7) + (((lane >> 3) & 1) << 3);
    int ka = lane >> 4;
    int rb = (lane & 7) + ((lane >> 4) << 3);
    int kb = (lane >> 3) & 1;
    #pragma unroll
    for (int ks = 0; ks < 4; ks++){
        uint32_t a[4][4], b[2][4];
        #pragma unroll
        for (int mf = 0; mf < 4; mf++){
            int row = wm*64 + mf*16 + ra;
            int kgr = ks*2 + ka;
            ldsm4(a[mf], smA + row*128 + ((kgr ^ (row & 7)) << 4));
        }
        #pragma unroll
        for (int nfp = 0; nfp < 2; nfp++){
            int row = wn*32 + nfp*16 + rb;
            int kgr = ks*2 + kb;
            ldsm4(b[nfp], smB + row*128 + ((kgr ^ (row & 7)) << 4));
        }
        #pragma unroll
        for (int mf = 0; mf < 4; mf++){
            mma16(acc[mf][0], a[mf], b[0] + 0);
            mma16(acc[mf][1], a[mf], b[0] + 2);
            mma16(acc[mf][2], a[mf], b[1] + 0);
            mma16(acc[mf][3], a[mf], b[1] + 2);
        }
    }
}

// ---------------- BN=64 mainloop compute (lora-A GEMMs) ----------------
__device__ __forceinline__ void stage_mma64(uint32_t smA, uint32_t smB,
                                            int lane, int wm, int wn,
                                            float (*acc)[4][4])   // acc[2][4][4]
{
    int ra = (lane & 7) + (((lane >> 3) & 1) << 3);
    int ka = lane >> 4;
    int rb = (lane & 7) + ((lane >> 4) << 3);
    int kb = (lane >> 3) & 1;
    #pragma unroll
    for (int ks = 0; ks < 4; ks++){
        uint32_t a[2][4], b[2][4];
        #pragma unroll
        for (int mf = 0; mf < 2; mf++){
            int row = wm*32 + mf*16 + ra;
            int kgr = ks*2 + ka;
            ldsm4(a[mf], smA + row*128 + ((kgr ^ (row & 7)) << 4));
        }
        #pragma unroll
        for (int nfp = 0; nfp < 2; nfp++){
            int row = wn*32 + nfp*16 + rb;
            int kgr = ks*2 + kb;
            ldsm4(b[nfp], smB + row*128 + ((kgr ^ (row & 7)) << 4));
        }
        #pragma unroll
        for (int mf = 0; mf < 2; mf++){
            mma16(acc[mf][0], a[mf], b[0] + 0);
            mma16(acc[mf][1], a[mf], b[0] + 2);
            mma16(acc[mf][2], a[mf], b[1] + 0);
            mma16(acc[mf][3], a[mf], b[1] + 2);
        }
    }
}

// ---------------- setup ----------------
__global__ void k_setup(const int* __restrict__ topk_ids, const float* __restrict__ topk_w,
                        const int* __restrict__ widx, const int* __restrict__ seq_lens,
                        const float* __restrict__ scalings)
{
    __shared__ int cnt[NEXP*NADP], off[NEXP*NADP], cur[NEXP*NADP], cum[NSEQ];
    int tid = threadIdx.x;
    if (tid < NEXP*NADP) cnt[tid] = 0;
    __syncthreads();
    if (tid == 0){ int c = 0; for (int s = 0; s < NSEQ; s++){ c += seq_lens[s]; cum[s] = c; } }
    __syncthreads();
    for (int p = tid; p < NPAIR; p += blockDim.x){
        int n = p / TOPK; int e = topk_ids[p];
        int s = 0; while (n >= cum[s]) s++;
        atomicAdd(&cnt[e*NADP + widx[s]], 1);
    }
    __syncthreads();
    if (tid == 0){
        int acc = 0;
        for (int k = 0; k < NEXP*NADP; k++){ off[k] = acc; cur[k] = acc; acc += cnt[k]; }
        int nt = 0;
        for (int e = 0; e < NEXP; e++){
            int base = off[e*NADP];
            int c = cnt[e*NADP] + cnt[e*NADP+1];
            for (int r0 = 0; r0 < c; r0 += BM){
                g2_e[nt] = e; g2_m0[nt] = base + r0; g2_rows[nt] = min(BM, c - r0); nt++;
            }
        }
        g2_ntiles = nt;
    }
    __syncthreads();
    for (int p = tid; p < NPAIR; p += blockDim.x){
        int n = p / TOPK; int e = topk_ids[p];
        int s = 0; while (n >= cum[s]) s++;
        int a = widx[s];
        int slot = atomicAdd(&cur[e*NADP + a], 1);
        g_tok[slot] = n; g_w[slot] = topk_w[p]; g_ad[slot] = a;
        g_scale[slot] = scalings[a]; g_exp[slot] = e;
    }
}

// ---------------- gather x rows (fp16) by slot ----------------
__global__ void k_gather(const float* __restrict__ x)
{
    int slot = blockIdx.x;
    int tok = g_tok[slot];
    int tid = threadIdx.x;                 // 256 threads, HID/4 = 256
    float4 v = ((const float4*)(x + (size_t)tok*HID))[tid];
    __half2* xh = (__half2*)(g_xg_h + (size_t)slot*HID);
    xh[2*tid]   = __float22half2_rn(make_float2(v.x, v.y));
    xh[2*tid+1] = __float22half2_rn(make_float2(v.z, v.w));
}

// ---------------- weight conversions fp32 -> fp16 ----------------
__global__ void k_convw(const float* __restrict__ wgu, const float* __restrict__ wd)
{
    const size_t n1 = (size_t)NEXP*2*ITR*HID/4;
    const size_t n2 = (size_t)NEXP*HID*ITR/4;
    size_t stride = (size_t)gridDim.x*blockDim.x;
    __half2* o1 = (__half2*)g_wgu_h;
    __half2* o2 = (__half2*)g_wd_h;
    for (size_t i = (size_t)blockIdx.x*blockDim.x + threadIdx.x; i < n1; i += stride){
        float4 v = ((const float4*)wgu)[i];
        o1[2*i]   = __float22half2_rn(make_float2(v.x, v.y));
        o1[2*i+1] = __float22half2_rn(make_float2(v.z, v.w));
    }
    for (size_t i = (size_t)blockIdx.x*blockDim.x + threadIdx.x; i < n2; i += stride){
        float4 v = ((const float4*)wd)[i];
        o2[2*i]   = __float22half2_rn(make_float2(v.x, v.y));
        o2[2*i+1] = __float22half2_rn(make_float2(v.z, v.w));
    }
}

// ---------------- prep: LoRA B extensions + LoRA A fp16 tiles (rank-masked) ----------------
__global__ void k_prep(const float* __restrict__ gate_a, const float* __restrict__ up_a,
                       const float* __restrict__ down_a,
                       const float* __restrict__ gb, const float* __restrict__ ub,
                       const float* __restrict__ db, const int* __restrict__ ranks)
{
    size_t stride = (size_t)gridDim.x*blockDim.x;
    int r0 = ranks[0], r1 = ranks[1];
    // B ext gate/up: [e][2*ITR rows (interleaved g/u)][64]
    const size_t n1 = (size_t)NEXP*2*ITR*64;
    for (size_t i = (size_t)blockIdx.x*blockDim.x + threadIdx.x; i < n1; i += stride){
        int c = (int)(i & 63);
        size_t R = (i >> 6);
        int e = (int)(R / (2*ITR));
        int r = (int)(R % (2*ITR));
        int j = r >> 1;
        float v = 0.f;
        if (!(r & 1)){
            if (c < 16) v = gb[((size_t)(0*NEXP + e)*ITR + j)*RNK + c];
            else if (c >= 32 && c < 48) v = gb[((size_t)(1*NEXP + e)*ITR + j)*RNK + (c - 32)];
        } else {
            if (c >= 16 && c < 32) v = ub[((size_t)(0*NEXP + e)*ITR + j)*RNK + (c - 16)];
            else if (c >= 48) v = ub[((size_t)(1*NEXP + e)*ITR + j)*RNK + (c - 48)];
        }
        g_bg_ext[i] = __float2half(v);
    }
    // B ext down: [e][HID][64]
    const size_t n2 = (size_t)NEXP*HID*64;
    for (size_t i = (size_t)blockIdx.x*blockDim.x + threadIdx.x; i < n2; i += stride){
        int c = (int)(i & 63);
        size_t R = (i >> 6);
        int e = (int)(R / HID);
        int h = (int)(R % HID);
        float v = 0.f;
        if (c < 16) v = db[((size_t)(0*NEXP + e)*HID + h)*RNK + c];
        else if (c < 32) v = db[((size_t)(1*NEXP + e)*HID + h)*RNK + (c - 16)];
        g_bd_ext[i] = __float2half(v);
    }
    // A1: [e][64][HID]  rows: ga0(16) ua0(16) ga1(16) ua1(16), rank-masked
    const size_t n3 = (size_t)NEXP*64*HID;
    for (size_t i = (size_t)blockIdx.x*blockDim.x + threadIdx.x; i < n3; i += stride){
        int h = (int)(i & (HID-1));
        size_t R = i >> 10;
        int e = (int)(R >> 6);
        int r = (int)(R & 63);
        int aidx = r >> 5, within = r & 31, type = within >> 4, rr = within & 15;
        int rk = aidx ? r1 : r0;
        float v = 0.f;
        if (rr < rk){
            const float* src = (type == 0 ? gate_a : up_a)
                + ((size_t)((aidx*NEXP + e)*RNK) + rr)*HID;
            v = src[h];
        }
        g_a1h[i] = __float2half(v);
    }
    // A2: [e][64][ITR]  rows: da0(16) da1(16) zeros(32), rank-masked
    const size_t n4 = (size_t)NEXP*64*ITR;
    for (size_t i = (size_t)blockIdx.x*blockDim.x + threadIdx.x; i < n4; i += stride){
        int h = (int)(i % ITR);
        size_t R = i / ITR;
        int e = (int)(R >> 6);
        int r = (int)(R & 63);
        float v = 0.f;
        if (r < 32){
            int aidx = r >> 4, rr = r & 15;
            int rk = aidx ? r1 : r0;
            if (rr < rk)
                v = down_a[((size_t)((aidx*NEXP + e)*RNK) + rr)*ITR + h];
        }
        g_a2h[i] = __float2half(v);
    }
}

// ---------------- lora-A GEMM fill ----------------
__device__ __forceinline__ void fillL(uint32_t smb, int s, int kc, int tid,
                                      const __half* Ab, int lda,
                                      const __half* Bb, int ldb)
{
    uint32_t ab = smb + s*LSTAGE;
    uint32_t bb = ab + 16384;
    #pragma unroll
    for (int q = 0; q < 4; q++){
        int G = tid + 256*q; int row = G >> 3, gr = G & 7;
        cpa16(ab + row*128 + ((gr ^ (row & 7)) << 4), Ab + (size_t)row*lda + kc*64 + gr*8);
    }
    #pragma unroll
    for (int q = 0; q < 2; q++){
        int G = tid + 256*q; int row = G >> 3, gr = G & 7;   // row 0..63
        cpa16(bb + row*128 + ((gr ^ (row & 7)) << 4), Bb + (size_t)row*ldb + kc*64 + gr*8);
    }
}

// ---------------- lora-A projections as tensor GEMM (mode 1: zgu, mode 2: zd) ----------------
__global__ __launch_bounds__(256, 2) void k_loraA(int mode)
{
    int t = blockIdx.x;
    if (t >= g2_ntiles) return;
    int e = g2_e[t], m0 = g2_m0[t], rows = g2_rows[t];

    const __half* Ab; const __half* Bb; int lda, nk;
    if (mode == 1){ Ab = g_xg_h + (size_t)m0*HID;  lda = HID; Bb = g_a1h + (size_t)e*64*HID; nk = 16; }
    else          { Ab = g_act_h + (size_t)m0*ITR; lda = ITR; Bb = g_a2h + (size_t)e*64*ITR; nk = 44; }

    extern __shared__ char smc[];
    uint32_t smb = s2u(smc);
    int tid = threadIdx.x, lane = tid & 31, wid = tid >> 5;
    int wm = wid & 3, wn = wid >> 2;

    float acc[2][4][4];
    #pragma unroll
    for (int i = 0; i < 2; i++)
        #pragma unroll
        for (int j = 0; j < 4; j++)
            #pragma unroll
            for (int k = 0; k < 4; k++) acc[i][j][k] = 0.f;

    fillL(smb, 0, 0, tid, Ab, lda, Bb, lda); cp_commit();
    for (int kc = 0; kc < nk; kc++){
        if (kc + 1 < nk){
            fillL(smb, (kc + 1) & 1, kc + 1, tid, Ab, lda, Bb, lda); cp_commit(); cp_wait1();
        } else cp_wait0();
        __syncthreads();
        uint32_t st = smb + (kc & 1)*LSTAGE;
        stage_mma64(st, st + 16384, lane, wm, wn, acc);
        __syncthreads();
    }

    int g = lane >> 2, tg = lane & 3;
    __half* outb = (mode == 1) ? g_zgu_h : g_zd_h;
    #pragma unroll
    for (int mf = 0; mf < 2; mf++){
        #pragma unroll
        for (int h = 0; h < 2; h++){
            int row = wm*32 + mf*16 + g + h*8;
            if (row >= rows) continue;
            int slot = m0 + row;
            int a = g_ad[slot];
            float sc = g_scale[slot];
            __half* orow = outb + (size_t)slot*64;
            #pragma unroll
            for (int nf = 0; nf < 4; nf++){
                #pragma unroll
                for (int p = 0; p < 2; p++){
                    int c = wn*32 + nf*8 + 2*tg + p;
                    float v = acc[mf][nf][h*2 + p];
                    bool keep = (mode == 1)
                        ? (a == 0 ? (c < 32) : (c >= 32))
                        : ((c < 16 && a == 0) || (c >= 16 && c < 32 && a == 1));
                    orow[c] = __float2half(keep ? sc*v : 0.f);
                }
            }
        }
    }
}

// ---------------- GEMM1 fill ----------------
__device__ __forceinline__ void fill1(uint32_t smb, int s, int kc, int tid,
                                      int e, int m0, int j064)
{
    uint32_t ab = smb + s*STAGEB;
    uint32_t bb = ab + 16384;
    #pragma unroll
    for (int q = 0; q < 4; q++){
        int G = tid + 256*q; int row = G >> 3, gr = G & 7;
        uint32_t off = row*128 + ((gr ^ (row & 7)) << 4);
        const __half* sa = (kc < 16)
            ? g_xg_h + (size_t)(m0 + row)*HID + kc*64 + gr*8
            : g_zgu_h + (size_t)(m0 + row)*64 + gr*8;
        cpa16(ab + off, sa);
        const __half* sb;
        if (kc < 16){
            int sr = ((row & 1) ? ITR : 0) + j064 + (row >> 1);
            sb = g_wgu_h + ((size_t)e*(2*ITR) + sr)*HID + kc*64 + gr*8;
        } else {
            sb = g_bg_ext + ((size_t)e*(2*ITR) + 2*j064 + row)*64 + gr*8;
        }
        cpa16(bb + off, sb);
    }
}

// ---------------- GEMM1: fused gate/up + LoRA + SiLU -> g_act_h ----------------
__global__ __launch_bounds__(256, 2) void k_gemm1()
{
    int t = blockIdx.x;
    if (t >= g2_ntiles) return;
    int e = g2_e[t], m0 = g2_m0[t], rows = g2_rows[t];
    int j064 = blockIdx.y * 64;

    extern __shared__ char smc[];
    uint32_t smb = s2u(smc);
    int tid = threadIdx.x, lane = tid & 31, wid = tid >> 5;
    int wm = wid & 1, wn = wid >> 1;

    float acc[4][4][4];
    #pragma unroll
    for (int i = 0; i < 4; i++)
        #pragma unroll
        for (int j = 0; j < 4; j++)
            #pragma unroll
            for (int k = 0; k < 4; k++) acc[i][j][k] = 0.f;

    fill1(smb, 0, 0, tid, e, m0, j064); cp_commit();
    for (int kc = 0; kc < NK1; kc++){
        if (kc + 1 < NK1){
            fill1(smb, (kc + 1) & 1, kc + 1, tid, e, m0, j064); cp_commit(); cp_wait1();
        } else cp_wait0();
        __syncthreads();
        uint32_t st = smb + (kc & 1)*STAGEB;
        stage_mma(st, st + 16384, lane, wm, wn, acc);
        __syncthreads();
    }

    int g = lane >> 2, tg = lane & 3;
    #pragma unroll
    for (int mf = 0; mf < 4; mf++){
        #pragma unroll
        for (int h = 0; h < 2; h++){
            int row = wm*64 + mf*16 + g + h*8;
            if (row >= rows) continue;
            __half* arow = g_act_h + (size_t)(m0 + row)*ITR + j064;
            #pragma unroll
            for (int nf = 0; nf < 4; nf++){
                float gate = acc[mf][nf][h*2 + 0];
                float up   = acc[mf][nf][h*2 + 1];
                float act = gate / (1.f + __expf(-gate)) * up;
                arow[wn*16 + nf*4 + tg] = __float2half(act);
            }
        }
    }
}

// ---------------- GEMM2 fill ----------------
__device__ __forceinline__ void fill2(uint32_t smb, int s, int kc, int tid,
                                      int e, int m0, int j0)
{
    uint32_t ab = smb + s*STAGEB;
    uint32_t bb = ab + 16384;
    #pragma unroll
    for (int q = 0; q < 4; q++){
        int G = tid + 256*q; int row = G >> 3, gr = G & 7;
        uint32_t off = row*128 + ((gr ^ (row & 7)) << 4);
        const __half* sa = (kc < 44)
            ? g_act_h + (size_t)(m0 + row)*ITR + kc*64 + gr*8
            : g_zd_h + (size_t)(m0 + row)*64 + gr*8;
        cpa16(ab + off, sa);
        const __half* sb = (kc < 44)
            ? g_wd_h + ((size_t)e*HID + j0 + row)*ITR + kc*64 + gr*8
            : g_bd_ext + ((size_t)e*HID + j0 + row)*64 + gr*8;
        cpa16(bb + off, sb);
    }
}

// ---------------- zero output ----------------
__global__ void k_zero(float* __restrict__ out)
{
    ((float4*)out)[blockIdx.x*256 + threadIdx.x] = make_float4(0.f, 0.f, 0.f, 0.f);
}

// ---------------- GEMM2: down proj + LoRA, weighted, atomic into out ----------------
__global__ __launch_bounds__(256, 2) void k_gemm2(float* __restrict__ out)
{
    int t = blockIdx.x;
    if (t >= g2_ntiles) return;
    int e = g2_e[t], m0 = g2_m0[t], rows = g2_rows[t];
    int j0 = blockIdx.y * BN;

    extern __shared__ char smc[];
    uint32_t smb = s2u(smc);
    __shared__ float s_wt[BM];
    __shared__ int   s_tok[BM];
    int tid = threadIdx.x, lane = tid & 31, wid = tid >> 5;
    int wm = wid & 1, wn = wid >> 1;
    if (tid < BM){
        int s = min(m0 + tid, NPAIR - 1);
        s_wt[tid] = g_w[s]; s_tok[tid] = g_tok[s];
    }

    float acc[4][4][4];
    #pragma unroll
    for (int i = 0; i < 4; i++)
        #pragma unroll
        for (int j = 0; j < 4; j++)
            #pragma unroll
            for (int k = 0; k < 4; k++) acc[i][j][k] = 0.f;

    fill2(smb, 0, 0, tid, e, m0, j0); cp_commit();
    for (int kc = 0; kc < NK2; kc++){
        if (kc + 1 < NK2){
            fill2(smb, (kc + 1) & 1, kc + 1, tid, e, m0, j0); cp_commit(); cp_wait1();
        } else cp_wait0();
        __syncthreads();
        uint32_t st = smb + (kc & 1)*STAGEB;
        stage_mma(st, st + 16384, lane, wm, wn, acc);
        __syncthreads();
    }

    int g = lane >> 2, tg = lane & 3;
    #pragma unroll
    for (int mf = 0; mf < 4; mf++){
        #pragma unroll
        for (int h = 0; h < 2; h++){
            int row = wm*64 + mf*16 + g + h*8;
            if (row >= rows) continue;
            float w = s_wt[row];
            float* orow = out + (size_t)s_tok[row]*HID + j0;
            #pragma unroll
            for (int nf = 0; nf < 4; nf++){
                int c = wn*32 + nf*8 + 2*tg;
                atomicAdd(orow + c,     w * acc[mf][nf][h*2 + 0]);
                atomicAdd(orow + c + 1, w * acc[mf][nf][h*2 + 1]);
            }
        }
    }
}

// ---------------- launch ----------------
extern "C" void kernel_launch(void* const* d_in, const int* in_sizes, int n_in,
                              void* d_out, int out_size)
{
    const float* x        = (const float*)d_in[0];
    const int*   topk_ids = (const int*)  d_in[1];
    const float* topk_w   = (const float*)d_in[2];
    const float* gate_a   = (const float*)d_in[3];
    const float* gate_b   = (const float*)d_in[4];
    const float* up_a     = (const float*)d_in[5];
    const float* up_b     = (const float*)d_in[6];
    const float* down_a   = (const float*)d_in[7];
    const float* down_b   = (const float*)d_in[8];
    const int*   widx     = (const int*)  d_in[9];
    const int*   seq_lens = (const int*)  d_in[10];
    const int*   ranks    = (const int*)  d_in[11];
    const float* scalings = (const float*)d_in[12];
    const float* Wgu      = (const float*)d_in[13];
    const float* Wd       = (const float*)d_in[14];
    float* out = (float*)d_out;

    static int s_attr_done = 0;
    if (!s_attr_done){
        cudaFuncSetAttribute(k_gemm1, cudaFuncAttributeMaxDynamicSharedMemorySize, SMEM_DYN);
        cudaFuncSetAttribute(k_gemm2, cudaFuncAttributeMaxDynamicSharedMemorySize, SMEM_DYN);
        cudaFuncSetAttribute(k_loraA, cudaFuncAttributeMaxDynamicSharedMemorySize, LSMEM);
        s_attr_done = 1;
    }

    k_setup<<<1, 256>>>(topk_ids, topk_w, widx, seq_lens, scalings);
    k_gather<<<NPAIR, 256>>>(x);
    k_convw<<<8192, 256>>>(Wgu, Wd);
    k_prep<<<2048, 256>>>(gate_a, up_a, down_a, gate_b, up_b, down_b, ranks);
    k_loraA<<<MAXT, 256, LSMEM>>>(1);
    k_gemm1<<<dim3(MAXT, NCT1), 256, SMEM_DYN>>>();
    k_loraA<<<MAXT, 256, LSMEM>>>(2);
    k_zero<<<NTOK*HID/1024, 256>>>(out);
    k_gemm2<<<dim3(MAXT, NCT2), 256, SMEM_DYN>>>(out);
}

// round 7
// speedup vs baseline: 8.6105x; 1.0064x over previous
#include <cuda_runtime.h>
#include <cuda_fp16.h>
#include <math.h>
#include <stdint.h>

// ---------------- problem constants ----------------
#define NTOK  2048
#define HID   1024
#define ITR   2816
#define NEXP  8
#define NADP  2
#define RNK   16
#define TOPK  2
#define NSEQ  8
#define NPAIR (NTOK*TOPK)        // 4096
#define NPAD  (NPAIR + 128)

// ---------------- GEMM tiling (mma.sync m16n8k16 fp16) ----------------
#define BM 128
#define BN 128
#define STAGEB 32768              // A tile 16KB + B tile 16KB
#define NSTG 3
#define SMEM_DYN (NSTG*STAGEB)    // 98304
#define NK1 17                    // 16 real + 1 lora-ext
#define NK2 45                    // 44 real + 1 lora-ext
#define MAXT (NPAIR/BM + NEXP)    // 40
#define NCT1 (ITR/64)             // 44
#define NCT2 (HID/BN)             // 8
// lora-A GEMM (N=64)
#define LSTAGE 24576              // A 16KB + B 8KB
#define LSMEM (NSTG*LSTAGE)       // 73728

// ---------------- device scratch ----------------
__device__ int   g_tok[NPAIR];
__device__ float g_w[NPAIR];
__device__ int   g_ad[NPAIR];
__device__ float g_scale[NPAIR];
__device__ int   g_exp[NPAIR];
__device__ int   g2_ntiles;
__device__ int   g2_e[MAXT];
__device__ int   g2_m0[MAXT];
__device__ int   g2_rows[MAXT];
__device__ __align__(16) __half g_xg_h[(size_t)NPAD*HID];
__device__ __align__(16) __half g_act_h[(size_t)NPAD*ITR];
__device__ __align__(16) __half g_zgu_h[(size_t)NPAD*64];
__device__ __align__(16) __half g_zd_h[(size_t)NPAD*64];
__device__ __align__(16) __half g_wgu_h[(size_t)NEXP*2*ITR*HID];
__device__ __align__(16) __half g_wd_h[(size_t)NEXP*HID*ITR];
__device__ __align__(16) __half g_bg_ext[(size_t)NEXP*2*ITR*64];
__device__ __align__(16) __half g_bd_ext[(size_t)NEXP*HID*64];
__device__ __align__(16) __half g_a1h[(size_t)NEXP*64*HID];   // [e][ga0|ua0|ga1|ua1][HID]
__device__ __align__(16) __half g_a2h[(size_t)NEXP*64*ITR];   // [e][da0|da1|zeros][ITR]

// ---------------- PTX helpers ----------------
__device__ __forceinline__ uint32_t s2u(const void* p){
    uint32_t a;
    asm("{ .reg .u64 t; cvta.to.shared.u64 t, %1; cvt.u32.u64 %0, t; }":"=r"(a):"l"(p));
    return a;
}
__device__ __forceinline__ void cpa16(uint32_t dst, const void* src){
    asm volatile("cp.async.cg.shared.global [%0], [%1], 16;" :: "r"(dst), "l"(src));
}
__device__ __forceinline__ void cp_commit(){ asm volatile("cp.async.commit_group;":::"memory"); }
__device__ __forceinline__ void cp_wait1(){ asm volatile("cp.async.wait_group 1;":::"memory"); }
__device__ __forceinline__ void ldsm4(uint32_t* r, uint32_t addr){
    asm volatile("ldmatrix.sync.aligned.m8n8.x4.shared.b16 {%0,%1,%2,%3}, [%4];"
      : "=r"(r[0]),"=r"(r[1]),"=r"(r[2]),"=r"(r[3]) : "r"(addr));
}
__device__ __forceinline__ void mma16(float* c, const uint32_t* a, const uint32_t* b){
    asm volatile("mma.sync.aligned.m16n8k16.row.col.f32.f16.f16.f32 "
      "{%0,%1,%2,%3},{%4,%5,%6,%7},{%8,%9},{%0,%1,%2,%3};"
      : "+f"(c[0]),"+f"(c[1]),"+f"(c[2]),"+f"(c[3])
      : "r"(a[0]),"r"(a[1]),"r"(a[2]),"r"(a[3]),"r"(b[0]),"r"(b[1]));
}

// ---------------- BN=128 mainloop compute ----------------
__device__ __forceinline__ void stage_mma(uint32_t smA, uint32_t smB,
                                          int lane, int wm, int wn,
                                          float (*acc)[4][4])
{
    int ra = (lane & 7) + (((lane >> 3) & 1) << 3);
    int ka = lane >> 4;
    int rb = (lane & 7) + ((lane >> 4) << 3);
    int kb = (lane >> 3) & 1;
    #pragma unroll
    for (int ks = 0; ks < 4; ks++){
        uint32_t a[4][4], b[2][4];
        #pragma unroll
        for (int mf = 0; mf < 4; mf++){
            int row = wm*64 + mf*16 + ra;
            int kgr = ks*2 + ka;
            ldsm4(a[mf], smA + row*128 + ((kgr ^ (row & 7)) << 4));
        }
        #pragma unroll
        for (int nfp = 0; nfp < 2; nfp++){
            int row = wn*32 + nfp*16 + rb;
            int kgr = ks*2 + kb;
            ldsm4(b[nfp], smB + row*128 + ((kgr ^ (row & 7)) << 4));
        }
        #pragma unroll
        for (int mf = 0; mf < 4; mf++){
            mma16(acc[mf][0], a[mf], b[0] + 0);
            mma16(acc[mf][1], a[mf], b[0] + 2);
            mma16(acc[mf][2], a[mf], b[1] + 0);
            mma16(acc[mf][3], a[mf], b[1] + 2);
        }
    }
}

// ---------------- BN=64 mainloop compute (lora-A GEMMs) ----------------
__device__ __forceinline__ void stage_mma64(uint32_t smA, uint32_t smB,
                                            int lane, int wm, int wn,
                                            float (*acc)[4][4])   // acc[2][4][4]
{
    int ra = (lane & 7) + (((lane >> 3) & 1) << 3);
    int ka = lane >> 4;
    int rb = (lane & 7) + ((lane >> 4) << 3);
    int kb = (lane >> 3) & 1;
    #pragma unroll
    for (int ks = 0; ks < 4; ks++){
        uint32_t a[2][4], b[2][4];
        #pragma unroll
        for (int mf = 0; mf < 2; mf++){
            int row = wm*32 + mf*16 + ra;
            int kgr = ks*2 + ka;
            ldsm4(a[mf], smA + row*128 + ((kgr ^ (row & 7)) << 4));
        }
        #pragma unroll
        for (int nfp = 0; nfp < 2; nfp++){
            int row = wn*32 + nfp*16 + rb;
            int kgr = ks*2 + kb;
            ldsm4(b[nfp], smB + row*128 + ((kgr ^ (row & 7)) << 4));
        }
        #pragma unroll
        for (int mf = 0; mf < 2; mf++){
            mma16(acc[mf][0], a[mf], b[0] + 0);
            mma16(acc[mf][1], a[mf], b[0] + 2);
            mma16(acc[mf][2], a[mf], b[1] + 0);
            mma16(acc[mf][3], a[mf], b[1] + 2);
        }
    }
}

// ---------------- setup ----------------
__global__ void k_setup(const int* __restrict__ topk_ids, const float* __restrict__ topk_w,
                        const int* __restrict__ widx, const int* __restrict__ seq_lens,
                        const float* __restrict__ scalings)
{
    __shared__ int cnt[NEXP*NADP], off[NEXP*NADP], cur[NEXP*NADP], cum[NSEQ];
    int tid = threadIdx.x;
    if (tid < NEXP*NADP) cnt[tid] = 0;
    __syncthreads();
    if (tid == 0){ int c = 0; for (int s = 0; s < NSEQ; s++){ c += seq_lens[s]; cum[s] = c; } }
    __syncthreads();
    for (int p = tid; p < NPAIR; p += blockDim.x){
        int n = p / TOPK; int e = topk_ids[p];
        int s = 0; while (n >= cum[s]) s++;
        atomicAdd(&cnt[e*NADP + widx[s]], 1);
    }
    __syncthreads();
    if (tid == 0){
        int acc = 0;
        for (int k = 0; k < NEXP*NADP; k++){ off[k] = acc; cur[k] = acc; acc += cnt[k]; }
        int nt = 0;
        for (int e = 0; e < NEXP; e++){
            int base = off[e*NADP];
            int c = cnt[e*NADP] + cnt[e*NADP+1];
            for (int r0 = 0; r0 < c; r0 += BM){
                g2_e[nt] = e; g2_m0[nt] = base + r0; g2_rows[nt] = min(BM, c - r0); nt++;
            }
        }
        g2_ntiles = nt;
    }
    __syncthreads();
    for (int p = tid; p < NPAIR; p += blockDim.x){
        int n = p / TOPK; int e = topk_ids[p];
        int s = 0; while (n >= cum[s]) s++;
        int a = widx[s];
        int slot = atomicAdd(&cur[e*NADP + a], 1);
        g_tok[slot] = n; g_w[slot] = topk_w[p]; g_ad[slot] = a;
        g_scale[slot] = scalings[a]; g_exp[slot] = e;
    }
}

// ---------------- fused prep: convw + lora tiles + gather + zero out ----------------
__global__ void k_preall(const float* __restrict__ x,
                         const float* __restrict__ wgu, const float* __restrict__ wd,
                         const float* __restrict__ gate_a, const float* __restrict__ up_a,
                         const float* __restrict__ down_a,
                         const float* __restrict__ gb, const float* __restrict__ ub,
                         const float* __restrict__ db, const int* __restrict__ ranks,
                         float* __restrict__ out)
{
    size_t stride = (size_t)gridDim.x*blockDim.x;
    size_t tid0 = (size_t)blockIdx.x*blockDim.x + threadIdx.x;
    int r0 = ranks[0], r1 = ranks[1];

    // 1) weight conversions
    {
        const size_t n1 = (size_t)NEXP*2*ITR*HID/4;
        __half2* o1 = (__half2*)g_wgu_h;
        for (size_t i = tid0; i < n1; i += stride){
            float4 v = ((const float4*)wgu)[i];
            o1[2*i]   = __float22half2_rn(make_float2(v.x, v.y));
            o1[2*i+1] = __float22half2_rn(make_float2(v.z, v.w));
        }
        const size_t n2 = (size_t)NEXP*HID*ITR/4;
        __half2* o2 = (__half2*)g_wd_h;
        for (size_t i = tid0; i < n2; i += stride){
            float4 v = ((const float4*)wd)[i];
            o2[2*i]   = __float22half2_rn(make_float2(v.x, v.y));
            o2[2*i+1] = __float22half2_rn(make_float2(v.z, v.w));
        }
    }
    // 2) gather x rows to fp16 by slot
    {
        const size_t n = (size_t)NPAIR*(HID/4);
        for (size_t i = tid0; i < n; i += stride){
            int slot = (int)(i >> 8);
            int c = (int)(i & 255);
            float4 v = ((const float4*)(x + (size_t)g_tok[slot]*HID))[c];
            __half2* xh = (__half2*)(g_xg_h + (size_t)slot*HID);
            xh[2*c]   = __float22half2_rn(make_float2(v.x, v.y));
            xh[2*c+1] = __float22half2_rn(make_float2(v.z, v.w));
        }
    }
    // 3) zero output
    {
        const size_t n = (size_t)NTOK*HID/4;
        for (size_t i = tid0; i < n; i += stride)
            ((float4*)out)[i] = make_float4(0.f, 0.f, 0.f, 0.f);
    }
    // 4) B ext gate/up
    {
        const size_t n1 = (size_t)NEXP*2*ITR*64;
        for (size_t i = tid0; i < n1; i += stride){
            int c = (int)(i & 63);
            size_t R = (i >> 6);
            int e = (int)(R / (2*ITR));
            int r = (int)(R % (2*ITR));
            int j = r >> 1;
            float v = 0.f;
            if (!(r & 1)){
                if (c < 16) v = gb[((size_t)(0*NEXP + e)*ITR + j)*RNK + c];
                else if (c >= 32 && c < 48) v = gb[((size_t)(1*NEXP + e)*ITR + j)*RNK + (c - 32)];
            } else {
                if (c >= 16 && c < 32) v = ub[((size_t)(0*NEXP + e)*ITR + j)*RNK + (c - 16)];
                else if (c >= 48) v = ub[((size_t)(1*NEXP + e)*ITR + j)*RNK + (c - 48)];
            }
            g_bg_ext[i] = __float2half(v);
        }
    }
    // 5) B ext down
    {
        const size_t n2 = (size_t)NEXP*HID*64;
        for (size_t i = tid0; i < n2; i += stride){
            int c = (int)(i & 63);
            size_t R = (i >> 6);
            int e = (int)(R / HID);
            int h = (int)(R % HID);
            float v = 0.f;
            if (c < 16) v = db[((size_t)(0*NEXP + e)*HID + h)*RNK + c];
            else if (c < 32) v = db[((size_t)(1*NEXP + e)*HID + h)*RNK + (c - 16)];
            g_bd_ext[i] = __float2half(v);
        }
    }
    // 6) A1 tiles
    {
        const size_t n3 = (size_t)NEXP*64*HID;
        for (size_t i = tid0; i < n3; i += stride){
            int h = (int)(i & (HID-1));
            size_t R = i >> 10;
            int e = (int)(R >> 6);
            int r = (int)(R & 63);
            int aidx = r >> 5, within = r & 31, type = within >> 4, rr = within & 15;
            int rk = aidx ? r1 : r0;
            float v = 0.f;
            if (rr < rk){
                const float* src = (type == 0 ? gate_a : up_a)
                    + ((size_t)((aidx*NEXP + e)*RNK) + rr)*HID;
                v = src[h];
            }
            g_a1h[i] = __float2half(v);
        }
    }
    // 7) A2 tiles
    {
        const size_t n4 = (size_t)NEXP*64*ITR;
        for (size_t i = tid0; i < n4; i += stride){
            int h = (int)(i % ITR);
            size_t R = i / ITR;
            int e = (int)(R >> 6);
            int r = (int)(R & 63);
            float v = 0.f;
            if (r < 32){
                int aidx = r >> 4, rr = r & 15;
                int rk = aidx ? r1 : r0;
                if (rr < rk)
                    v = down_a[((size_t)((aidx*NEXP + e)*RNK) + rr)*ITR + h];
            }
            g_a2h[i] = __float2half(v);
        }
    }
}

// ---------------- lora-A GEMM fill ----------------
__device__ __forceinline__ void fillL(uint32_t smb, int s, int kc, int tid,
                                      const __half* Ab, int lda, const __half* Bb)
{
    uint32_t ab = smb + s*LSTAGE;
    uint32_t bb = ab + 16384;
    #pragma unroll
    for (int q = 0; q < 4; q++){
        int G = tid + 256*q; int row = G >> 3, gr = G & 7;
        cpa16(ab + row*128 + ((gr ^ (row & 7)) << 4), Ab + (size_t)row*lda + kc*64 + gr*8);
    }
    #pragma unroll
    for (int q = 0; q < 2; q++){
        int G = tid + 256*q; int row = G >> 3, gr = G & 7;   // row 0..63
        cpa16(bb + row*128 + ((gr ^ (row & 7)) << 4), Bb + (size_t)row*lda + kc*64 + gr*8);
    }
}

// ---------------- lora-A projections as tensor GEMM (mode 1: zgu, mode 2: zd) ----------------
__global__ __launch_bounds__(256, 2) void k_loraA(int mode)
{
    int t = blockIdx.x;
    if (t >= g2_ntiles) return;
    int e = g2_e[t], m0 = g2_m0[t], rows = g2_rows[t];

    const __half* Ab; const __half* Bb; int lda, nk;
    if (mode == 1){ Ab = g_xg_h + (size_t)m0*HID;  lda = HID; Bb = g_a1h + (size_t)e*64*HID; nk = 16; }
    else          { Ab = g_act_h + (size_t)m0*ITR; lda = ITR; Bb = g_a2h + (size_t)e*64*ITR; nk = 44; }

    extern __shared__ char smc[];
    uint32_t smb = s2u(smc);
    int tid = threadIdx.x, lane = tid & 31, wid = tid >> 5;
    int wm = wid & 3, wn = wid >> 2;

    float acc[2][4][4];
    #pragma unroll
    for (int i = 0; i < 2; i++)
        #pragma unroll
        for (int j = 0; j < 4; j++)
            #pragma unroll
            for (int k = 0; k < 4; k++) acc[i][j][k] = 0.f;

    fillL(smb, 0, 0, tid, Ab, lda, Bb); cp_commit();
    fillL(smb, 1, 1, tid, Ab, lda, Bb); cp_commit();
    int sC = 0, sF = 2;
    for (int kc = 0; kc < nk; kc++){
        cp_wait1();
        __syncthreads();
        if (kc + 2 < nk){ fillL(smb, sF, kc + 2, tid, Ab, lda, Bb); }
        cp_commit();
        uint32_t st = smb + sC*LSTAGE;
        stage_mma64(st, st + 16384, lane, wm, wn, acc);
        sC = (sC == 2) ? 0 : sC + 1;
        sF = (sF == 2) ? 0 : sF + 1;
        __syncthreads();
    }

    int g = lane >> 2, tg = lane & 3;
    __half* outb = (mode == 1) ? g_zgu_h : g_zd_h;
    #pragma unroll
    for (int mf = 0; mf < 2; mf++){
        #pragma unroll
        for (int h = 0; h < 2; h++){
            int row = wm*32 + mf*16 + g + h*8;
            if (row >= rows) continue;
            int slot = m0 + row;
            int a = g_ad[slot];
            float sc = g_scale[slot];
            __half* orow = outb + (size_t)slot*64;
            #pragma unroll
            for (int nf = 0; nf < 4; nf++){
                #pragma unroll
                for (int p = 0; p < 2; p++){
                    int c = wn*32 + nf*8 + 2*tg + p;
                    float v = acc[mf][nf][h*2 + p];
                    bool keep = (mode == 1)
                        ? (a == 0 ? (c < 32) : (c >= 32))
                        : ((c < 16 && a == 0) || (c >= 16 && c < 32 && a == 1));
                    orow[c] = __float2half(keep ? sc*v : 0.f);
                }
            }
        }
    }
}

// ---------------- GEMM1 fill ----------------
__device__ __forceinline__ void fill1(uint32_t smb, int s, int kc, int tid,
                                      int e, int m0, int j064)
{
    uint32_t ab = smb + s*STAGEB;
    uint32_t bb = ab + 16384;
    #pragma unroll
    for (int q = 0; q < 4; q++){
        int G = tid + 256*q; int row = G >> 3, gr = G & 7;
        uint32_t off = row*128 + ((gr ^ (row & 7)) << 4);
        const __half* sa = (kc < 16)
            ? g_xg_h + (size_t)(m0 + row)*HID + kc*64 + gr*8
            : g_zgu_h + (size_t)(m0 + row)*64 + gr*8;
        cpa16(ab + off, sa);
        const __half* sb;
        if (kc < 16){
            int sr = ((row & 1) ? ITR : 0) + j064 + (row >> 1);
            sb = g_wgu_h + ((size_t)e*(2*ITR) + sr)*HID + kc*64 + gr*8;
        } else {
            sb = g_bg_ext + ((size_t)e*(2*ITR) + 2*j064 + row)*64 + gr*8;
        }
        cpa16(bb + off, sb);
    }
}

// ---------------- GEMM1: fused gate/up + LoRA + SiLU -> g_act_h ----------------
__global__ __launch_bounds__(256, 2) void k_gemm1()
{
    int t = blockIdx.x;
    if (t >= g2_ntiles) return;
    int e = g2_e[t], m0 = g2_m0[t], rows = g2_rows[t];
    int j064 = blockIdx.y * 64;

    extern __shared__ char smc[];
    uint32_t smb = s2u(smc);
    int tid = threadIdx.x, lane = tid & 31, wid = tid >> 5;
    int wm = wid & 1, wn = wid >> 1;

    float acc[4][4][4];
    #pragma unroll
    for (int i = 0; i < 4; i++)
        #pragma unroll
        for (int j = 0; j < 4; j++)
            #pragma unroll
            for (int k = 0; k < 4; k++) acc[i][j][k] = 0.f;

    fill1(smb, 0, 0, tid, e, m0, j064); cp_commit();
    fill1(smb, 1, 1, tid, e, m0, j064); cp_commit();
    int sC = 0, sF = 2;
    for (int kc = 0; kc < NK1; kc++){
        cp_wait1();
        __syncthreads();
        if (kc + 2 < NK1){ fill1(smb, sF, kc + 2, tid, e, m0, j064); }
        cp_commit();
        uint32_t st = smb + sC*STAGEB;
        stage_mma(st, st + 16384, lane, wm, wn, acc);
        sC = (sC == 2) ? 0 : sC + 1;
        sF = (sF == 2) ? 0 : sF + 1;
        __syncthreads();
    }

    int g = lane >> 2, tg = lane & 3;
    #pragma unroll
    for (int mf = 0; mf < 4; mf++){
        #pragma unroll
        for (int h = 0; h < 2; h++){
            int row = wm*64 + mf*16 + g + h*8;
            if (row >= rows) continue;
            __half* arow = g_act_h + (size_t)(m0 + row)*ITR + j064;
            #pragma unroll
            for (int nf = 0; nf < 4; nf++){
                float gate = acc[mf][nf][h*2 + 0];
                float up   = acc[mf][nf][h*2 + 1];
                float act = gate / (1.f + __expf(-gate)) * up;
                arow[wn*16 + nf*4 + tg] = __float2half(act);
            }
        }
    }
}

// ---------------- GEMM2 fill ----------------
__device__ __forceinline__ void fill2(uint32_t smb, int s, int kc, int tid,
                                      int e, int m0, int j0)
{
    uint32_t ab = smb + s*STAGEB;
    uint32_t bb = ab + 16384;
    #pragma unroll
    for (int q = 0; q < 4; q++){
        int G = tid + 256*q; int row = G >> 3, gr = G & 7;
        uint32_t off = row*128 + ((gr ^ (row & 7)) << 4);
        const __half* sa = (kc < 44)
            ? g_act_h + (size_t)(m0 + row)*ITR + kc*64 + gr*8
            : g_zd_h + (size_t)(m0 + row)*64 + gr*8;
        cpa16(ab + off, sa);
        const __half* sb = (kc < 44)
            ? g_wd_h + ((size_t)e*HID + j0 + row)*ITR + kc*64 + gr*8
            : g_bd_ext + ((size_t)e*HID + j0 + row)*64 + gr*8;
        cpa16(bb + off, sb);
    }
}

// ---------------- GEMM2: down proj + LoRA, weighted, atomic into out ----------------
__global__ __launch_bounds__(256, 2) void k_gemm2(float* __restrict__ out)
{
    int t = blockIdx.x;
    if (t >= g2_ntiles) return;
    int e = g2_e[t], m0 = g2_m0[t], rows = g2_rows[t];
    int j0 = blockIdx.y * BN;

    extern __shared__ char smc[];
    uint32_t smb = s2u(smc);
    __shared__ float s_wt[BM];
    __shared__ int   s_tok[BM];
    int tid = threadIdx.x, lane = tid & 31, wid = tid >> 5;
    int wm = wid & 1, wn = wid >> 1;
    if (tid < BM){
        int s = min(m0 + tid, NPAIR - 1);
        s_wt[tid] = g_w[s]; s_tok[tid] = g_tok[s];
    }

    float acc[4][4][4];
    #pragma unroll
    for (int i = 0; i < 4; i++)
        #pragma unroll
        for (int j = 0; j < 4; j++)
            #pragma unroll
            for (int k = 0; k < 4; k++) acc[i][j][k] = 0.f;

    fill2(smb, 0, 0, tid, e, m0, j0); cp_commit();
    fill2(smb, 1, 1, tid, e, m0, j0); cp_commit();
    int sC = 0, sF = 2;
    for (int kc = 0; kc < NK2; kc++){
        cp_wait1();
        __syncthreads();
        if (kc + 2 < NK2){ fill2(smb, sF, kc + 2, tid, e, m0, j0); }
        cp_commit();
        uint32_t st = smb + sC*STAGEB;
        stage_mma(st, st + 16384, lane, wm, wn, acc);
        sC = (sC == 2) ? 0 : sC + 1;
        sF = (sF == 2) ? 0 : sF + 1;
        __syncthreads();
    }

    int g = lane >> 2, tg = lane & 3;
    #pragma unroll
    for (int mf = 0; mf < 4; mf++){
        #pragma unroll
        for (int h = 0; h < 2; h++){
            int row = wm*64 + mf*16 + g + h*8;
            if (row >= rows) continue;
            float w = s_wt[row];
            float* orow = out + (size_t)s_tok[row]*HID + j0;
            #pragma unroll
            for (int nf = 0; nf < 4; nf++){
                int c = wn*32 + nf*8 + 2*tg;
                atomicAdd(orow + c,     w * acc[mf][nf][h*2 + 0]);
                atomicAdd(orow + c + 1, w * acc[mf][nf][h*2 + 1]);
            }
        }
    }
}

// ---------------- launch ----------------
extern "C" void kernel_launch(void* const* d_in, const int* in_sizes, int n_in,
                              void* d_out, int out_size)
{
    const float* x        = (const float*)d_in[0];
    const int*   topk_ids = (const int*)  d_in[1];
    const float* topk_w   = (const float*)d_in[2];
    const float* gate_a   = (const float*)d_in[3];
    const float* gate_b   = (const float*)d_in[4];
    const float* up_a     = (const float*)d_in[5];
    const float* up_b     = (const float*)d_in[6];
    const float* down_a   = (const float*)d_in[7];
    const float* down_b   = (const float*)d_in[8];
    const int*   widx     = (const int*)  d_in[9];
    const int*   seq_lens = (const int*)  d_in[10];
    const int*   ranks    = (const int*)  d_in[11];
    const float* scalings = (const float*)d_in[12];
    const float* Wgu      = (const float*)d_in[13];
    const float* Wd       = (const float*)d_in[14];
    float* out = (float*)d_out;

    static int s_attr_done = 0;
    if (!s_attr_done){
        cudaFuncSetAttribute(k_gemm1, cudaFuncAttributeMaxDynamicSharedMemorySize, SMEM_DYN);
        cudaFuncSetAttribute(k_gemm2, cudaFuncAttributeMaxDynamicSharedMemorySize, SMEM_DYN);
        cudaFuncSetAttribute(k_loraA, cudaFuncAttributeMaxDynamicSharedMemorySize, LSMEM);
        s_attr_done = 1;
    }

    k_setup<<<1, 256>>>(topk_ids, topk_w, widx, seq_lens, scalings);
    k_preall<<<8192, 256>>>(x, Wgu, Wd, gate_a, up_a, down_a,
                            gate_b, up_b, down_b, ranks, out);
    k_loraA<<<MAXT, 256, LSMEM>>>(1);
    k_gemm1<<<dim3(MAXT, NCT1), 256, SMEM_DYN>>>();
    k_loraA<<<MAXT, 256, LSMEM>>>(2);
    k_gemm2<<<dim3(MAXT, NCT2), 256, SMEM_DYN>>>(out);
}

// round 8
// speedup vs baseline: 8.9007x; 1.0337x over previous
#include <cuda_runtime.h>
#include <cuda_fp16.h>
#include <math.h>
#include <stdint.h>

// ---------------- problem constants ----------------
#define NTOK  2048
#define HID   1024
#define ITR   2816
#define NEXP  8
#define NADP  2
#define RNK   16
#define TOPK  2
#define NSEQ  8
#define NPAIR (NTOK*TOPK)        // 4096
#define NPAD  (NPAIR + 128)

// ---------------- GEMM tiling (mma.sync m16n8k16 fp16) ----------------
#define BM 128
#define BN 128
#define STAGEB 32768              // A tile 16KB + B tile 16KB
#define NSTG 3
#define SMEM_DYN (NSTG*STAGEB)    // 98304
#define NK1 17                    // 16 real + 1 lora-ext
#define NK2 45                    // 44 real + 1 lora-ext
#define MAXT (NPAIR/BM + NEXP)    // 40
#define NCT1 (ITR/64)             // 44
#define NCT2 (HID/BN)             // 8
#define NEY  4                    // extra y-rows in gemm1 doing Wd conversion
// lora-A GEMM (N=64)
#define LSTAGE 24576              // A 16KB + B 8KB
#define LSMEM (NSTG*LSTAGE)       // 73728
#define NCV1 216                  // extra blocks in loraA(1) doing Wgu conversion

// ---------------- device scratch ----------------
__device__ int   g_tok[NPAIR];
__device__ float g_w[NPAIR];
__device__ int   g_ad[NPAIR];
__device__ float g_scale[NPAIR];
__device__ int   g2_ntiles;
__device__ int   g2_e[MAXT];
__device__ int   g2_m0[MAXT];
__device__ int   g2_rows[MAXT];
__device__ __align__(16) __half g_xg_h[(size_t)NPAD*HID];
__device__ __align__(16) __half g_act_h[(size_t)NPAD*ITR];
__device__ __align__(16) __half g_zgu_h[(size_t)NPAD*64];
__device__ __align__(16) __half g_zd_h[(size_t)NPAD*64];
__device__ __align__(16) __half g_wgu_h[(size_t)NEXP*2*ITR*HID];
__device__ __align__(16) __half g_wd_h[(size_t)NEXP*HID*ITR];
__device__ __align__(16) __half g_bg_ext[(size_t)NEXP*2*ITR*64];
__device__ __align__(16) __half g_bd_ext[(size_t)NEXP*HID*64];
__device__ __align__(16) __half g_a1h[(size_t)NEXP*64*HID];   // [e][ga0|ua0|ga1|ua1][HID]
__device__ __align__(16) __half g_a2h[(size_t)NEXP*64*ITR];   // [e][da0|da1|zeros][ITR]

// ---------------- PTX helpers ----------------
__device__ __forceinline__ uint32_t s2u(const void* p){
    uint32_t a;
    asm("{ .reg .u64 t; cvta.to.shared.u64 t, %1; cvt.u32.u64 %0, t; }":"=r"(a):"l"(p));
    return a;
}
__device__ __forceinline__ void cpa16(uint32_t dst, const void* src){
    asm volatile("cp.async.cg.shared.global [%0], [%1], 16;" :: "r"(dst), "l"(src));
}
__device__ __forceinline__ void cp_commit(){ asm volatile("cp.async.commit_group;":::"memory"); }
__device__ __forceinline__ void cp_wait1(){ asm volatile("cp.async.wait_group 1;":::"memory"); }
__device__ __forceinline__ void ldsm4(uint32_t* r, uint32_t addr){
    asm volatile("ldmatrix.sync.aligned.m8n8.x4.shared.b16 {%0,%1,%2,%3}, [%4];"
      : "=r"(r[0]),"=r"(r[1]),"=r"(r[2]),"=r"(r[3]) : "r"(addr));
}
__device__ __forceinline__ void mma16(float* c, const uint32_t* a, const uint32_t* b){
    asm volatile("mma.sync.aligned.m16n8k16.row.col.f32.f16.f16.f32 "
      "{%0,%1,%2,%3},{%4,%5,%6,%7},{%8,%9},{%0,%1,%2,%3};"
      : "+f"(c[0]),"+f"(c[1]),"+f"(c[2]),"+f"(c[3])
      : "r"(a[0]),"r"(a[1]),"r"(a[2]),"r"(a[3]),"r"(b[0]),"r"(b[1]));
}

// ---------------- BN=128 mainloop compute ----------------
__device__ __forceinline__ void stage_mma(uint32_t smA, uint32_t smB,
                                          int lane, int wm, int wn,
                                          float (*acc)[4][4])
{
    int ra = (lane & 7) + (((lane >> 3) & 1) << 3);
    int ka = lane >> 4;
    int rb = (lane & 7) + ((lane >> 4) << 3);
    int kb = (lane >> 3) & 1;
    #pragma unroll
    for (int ks = 0; ks < 4; ks++){
        uint32_t a[4][4], b[2][4];
        #pragma unroll
        for (int mf = 0; mf < 4; mf++){
            int row = wm*64 + mf*16 + ra;
            int kgr = ks*2 + ka;
            ldsm4(a[mf], smA + row*128 + ((kgr ^ (row & 7)) << 4));
        }
        #pragma unroll
        for (int nfp = 0; nfp < 2; nfp++){
            int row = wn*32 + nfp*16 + rb;
            int kgr = ks*2 + kb;
            ldsm4(b[nfp], smB + row*128 + ((kgr ^ (row & 7)) << 4));
        }
        #pragma unroll
        for (int mf = 0; mf < 4; mf++){
            mma16(acc[mf][0], a[mf], b[0] + 0);
            mma16(acc[mf][1], a[mf], b[0] + 2);
            mma16(acc[mf][2], a[mf], b[1] + 0);
            mma16(acc[mf][3], a[mf], b[1] + 2);
        }
    }
}

// ---------------- BN=64 mainloop compute (lora-A GEMMs) ----------------
__device__ __forceinline__ void stage_mma64(uint32_t smA, uint32_t smB,
                                            int lane, int wm, int wn,
                                            float (*acc)[4][4])   // acc[2][4][4]
{
    int ra = (lane & 7) + (((lane >> 3) & 1) << 3);
    int ka = lane >> 4;
    int rb = (lane & 7) + ((lane >> 4) << 3);
    int kb = (lane >> 3) & 1;
    #pragma unroll
    for (int ks = 0; ks < 4; ks++){
        uint32_t a[2][4], b[2][4];
        #pragma unroll
        for (int mf = 0; mf < 2; mf++){
            int row = wm*32 + mf*16 + ra;
            int kgr = ks*2 + ka;
            ldsm4(a[mf], smA + row*128 + ((kgr ^ (row & 7)) << 4));
        }
        #pragma unroll
        for (int nfp = 0; nfp < 2; nfp++){
            int row = wn*32 + nfp*16 + rb;
            int kgr = ks*2 + kb;
            ldsm4(b[nfp], smB + row*128 + ((kgr ^ (row & 7)) << 4));
        }
        #pragma unroll
        for (int mf = 0; mf < 2; mf++){
            mma16(acc[mf][0], a[mf], b[0] + 0);
            mma16(acc[mf][1], a[mf], b[0] + 2);
            mma16(acc[mf][2], a[mf], b[1] + 0);
            mma16(acc[mf][3], a[mf], b[1] + 2);
        }
    }
}

// ---------------- setup ----------------
__global__ void k_setup(const int* __restrict__ topk_ids, const float* __restrict__ topk_w,
                        const int* __restrict__ widx, const int* __restrict__ seq_lens,
                        const float* __restrict__ scalings)
{
    __shared__ int cnt[NEXP*NADP], off[NEXP*NADP], cur[NEXP*NADP], cum[NSEQ];
    int tid = threadIdx.x;
    if (tid < NEXP*NADP) cnt[tid] = 0;
    __syncthreads();
    if (tid == 0){ int c = 0; for (int s = 0; s < NSEQ; s++){ c += seq_lens[s]; cum[s] = c; } }
    __syncthreads();
    for (int p = tid; p < NPAIR; p += blockDim.x){
        int n = p / TOPK; int e = topk_ids[p];
        int s = 0; while (n >= cum[s]) s++;
        atomicAdd(&cnt[e*NADP + widx[s]], 1);
    }
    __syncthreads();
    if (tid == 0){
        int acc = 0;
        for (int k = 0; k < NEXP*NADP; k++){ off[k] = acc; cur[k] = acc; acc += cnt[k]; }
        int nt = 0;
        for (int e = 0; e < NEXP; e++){
            int base = off[e*NADP];
            int c = cnt[e*NADP] + cnt[e*NADP+1];
            for (int r0 = 0; r0 < c; r0 += BM){
                g2_e[nt] = e; g2_m0[nt] = base + r0; g2_rows[nt] = min(BM, c - r0); nt++;
            }
        }
        g2_ntiles = nt;
    }
    __syncthreads();
    for (int p = tid; p < NPAIR; p += blockDim.x){
        int n = p / TOPK; int e = topk_ids[p];
        int s = 0; while (n >= cum[s]) s++;
        int a = widx[s];
        int slot = atomicAdd(&cur[e*NADP + a], 1);
        g_tok[slot] = n; g_w[slot] = topk_w[p]; g_ad[slot] = a;
        g_scale[slot] = scalings[a];
    }
}

// ---------------- prep: lora tiles + gather + zero (weight convs moved out) ----------------
__global__ void k_preall(const float* __restrict__ x,
                         const float* __restrict__ gate_a, const float* __restrict__ up_a,
                         const float* __restrict__ down_a,
                         const float* __restrict__ gb, const float* __restrict__ ub,
                         const float* __restrict__ db, const int* __restrict__ ranks,
                         float* __restrict__ out)
{
    size_t stride = (size_t)gridDim.x*blockDim.x;
    size_t tid0 = (size_t)blockIdx.x*blockDim.x + threadIdx.x;
    int r0 = ranks[0], r1 = ranks[1];

    // gather x rows to fp16 by slot
    {
        const size_t n = (size_t)NPAIR*(HID/4);
        for (size_t i = tid0; i < n; i += stride){
            int slot = (int)(i >> 8);
            int c = (int)(i & 255);
            float4 v = ((const float4*)(x + (size_t)g_tok[slot]*HID))[c];
            __half2* xh = (__half2*)(g_xg_h + (size_t)slot*HID);
            xh[2*c]   = __float22half2_rn(make_float2(v.x, v.y));
            xh[2*c+1] = __float22half2_rn(make_float2(v.z, v.w));
        }
    }
    // zero output
    {
        const size_t n = (size_t)NTOK*HID/4;
        for (size_t i = tid0; i < n; i += stride)
            ((float4*)out)[i] = make_float4(0.f, 0.f, 0.f, 0.f);
    }
    // B ext gate/up
    {
        const size_t n1 = (size_t)NEXP*2*ITR*64;
        for (size_t i = tid0; i < n1; i += stride){
            int c = (int)(i & 63);
            size_t R = (i >> 6);
            int e = (int)(R / (2*ITR));
            int r = (int)(R % (2*ITR));
            int j = r >> 1;
            float v = 0.f;
            if (!(r & 1)){
                if (c < 16) v = gb[((size_t)(0*NEXP + e)*ITR + j)*RNK + c];
                else if (c >= 32 && c < 48) v = gb[((size_t)(1*NEXP + e)*ITR + j)*RNK + (c - 32)];
            } else {
                if (c >= 16 && c < 32) v = ub[((size_t)(0*NEXP + e)*ITR + j)*RNK + (c - 16)];
                else if (c >= 48) v = ub[((size_t)(1*NEXP + e)*ITR + j)*RNK + (c - 48)];
            }
            g_bg_ext[i] = __float2half(v);
        }
    }
    // B ext down
    {
        const size_t n2 = (size_t)NEXP*HID*64;
        for (size_t i = tid0; i < n2; i += stride){
            int c = (int)(i & 63);
            size_t R = (i >> 6);
            int e = (int)(R / HID);
            int h = (int)(R % HID);
            float v = 0.f;
            if (c < 16) v = db[((size_t)(0*NEXP + e)*HID + h)*RNK + c];
            else if (c < 32) v = db[((size_t)(1*NEXP + e)*HID + h)*RNK + (c - 16)];
            g_bd_ext[i] = __float2half(v);
        }
    }
    // A1 tiles
    {
        const size_t n3 = (size_t)NEXP*64*HID;
        for (size_t i = tid0; i < n3; i += stride){
            int h = (int)(i & (HID-1));
            size_t R = i >> 10;
            int e = (int)(R >> 6);
            int r = (int)(R & 63);
            int aidx = r >> 5, within = r & 31, type = within >> 4, rr = within & 15;
            int rk = aidx ? r1 : r0;
            float v = 0.f;
            if (rr < rk){
                const float* src = (type == 0 ? gate_a : up_a)
                    + ((size_t)((aidx*NEXP + e)*RNK) + rr)*HID;
                v = src[h];
            }
            g_a1h[i] = __float2half(v);
        }
    }
    // A2 tiles
    {
        const size_t n4 = (size_t)NEXP*64*ITR;
        for (size_t i = tid0; i < n4; i += stride){
            int h = (int)(i % ITR);
            size_t R = i / ITR;
            int e = (int)(R >> 6);
            int r = (int)(R & 63);
            float v = 0.f;
            if (r < 32){
                int aidx = r >> 4, rr = r & 15;
                int rk = aidx ? r1 : r0;
                if (rr < rk)
                    v = down_a[((size_t)((aidx*NEXP + e)*RNK) + rr)*ITR + h];
            }
            g_a2h[i] = __float2half(v);
        }
    }
}

// ---------------- lora-A GEMM fill ----------------
__device__ __forceinline__ void fillL(uint32_t smb, int s, int kc, int tid,
                                      const __half* Ab, int lda, const __half* Bb)
{
    uint32_t ab = smb + s*LSTAGE;
    uint32_t bb = ab + 16384;
    #pragma unroll
    for (int q = 0; q < 4; q++){
        int G = tid + 256*q; int row = G >> 3, gr = G & 7;
        cpa16(ab + row*128 + ((gr ^ (row & 7)) << 4), Ab + (size_t)row*lda + kc*64 + gr*8);
    }
    #pragma unroll
    for (int q = 0; q < 2; q++){
        int G = tid + 256*q; int row = G >> 3, gr = G & 7;   // row 0..63
        cpa16(bb + row*128 + ((gr ^ (row & 7)) << 4), Bb + (size_t)row*lda + kc*64 + gr*8);
    }
}

// ---------------- lora-A GEMM (mode 1: zgu, mode 2: zd); extra blocks convert Wgu ----------------
__global__ __launch_bounds__(256, 2) void k_loraA(int mode, const float* __restrict__ wgu)
{
    int t = blockIdx.x;
    if (t >= MAXT){
        // conversion workers: fp32 Wgu -> fp16 (mode 1 only)
        if (mode != 1) return;
        size_t wi = (size_t)(t - MAXT)*blockDim.x + threadIdx.x;
        size_t nw = (size_t)(gridDim.x - MAXT)*blockDim.x;
        const size_t n1 = (size_t)NEXP*2*ITR*HID/4;
        __half2* o1 = (__half2*)g_wgu_h;
        for (size_t i = wi; i < n1; i += nw){
            float4 v = ((const float4*)wgu)[i];
            o1[2*i]   = __float22half2_rn(make_float2(v.x, v.y));
            o1[2*i+1] = __float22half2_rn(make_float2(v.z, v.w));
        }
        return;
    }
    if (t >= g2_ntiles) return;
    int e = g2_e[t], m0 = g2_m0[t], rows = g2_rows[t];

    const __half* Ab; const __half* Bb; int lda, nk;
    if (mode == 1){ Ab = g_xg_h + (size_t)m0*HID;  lda = HID; Bb = g_a1h + (size_t)e*64*HID; nk = 16; }
    else          { Ab = g_act_h + (size_t)m0*ITR; lda = ITR; Bb = g_a2h + (size_t)e*64*ITR; nk = 44; }

    extern __shared__ char smc[];
    uint32_t smb = s2u(smc);
    int tid = threadIdx.x, lane = tid & 31, wid = tid >> 5;
    int wm = wid & 3, wn = wid >> 2;

    float acc[2][4][4];
    #pragma unroll
    for (int i = 0; i < 2; i++)
        #pragma unroll
        for (int j = 0; j < 4; j++)
            #pragma unroll
            for (int k = 0; k < 4; k++) acc[i][j][k] = 0.f;

    fillL(smb, 0, 0, tid, Ab, lda, Bb); cp_commit();
    fillL(smb, 1, 1, tid, Ab, lda, Bb); cp_commit();
    int sC = 0, sF = 2;
    for (int kc = 0; kc < nk; kc++){
        cp_wait1();
        __syncthreads();
        if (kc + 2 < nk){ fillL(smb, sF, kc + 2, tid, Ab, lda, Bb); }
        cp_commit();
        uint32_t st = smb + sC*LSTAGE;
        stage_mma64(st, st + 16384, lane, wm, wn, acc);
        sC = (sC == 2) ? 0 : sC + 1;
        sF = (sF == 2) ? 0 : sF + 1;
    }

    int g = lane >> 2, tg = lane & 3;
    __half* outb = (mode == 1) ? g_zgu_h : g_zd_h;
    #pragma unroll
    for (int mf = 0; mf < 2; mf++){
        #pragma unroll
        for (int h = 0; h < 2; h++){
            int row = wm*32 + mf*16 + g + h*8;
            if (row >= rows) continue;
            int slot = m0 + row;
            int a = g_ad[slot];
            float sc = g_scale[slot];
            __half* orow = outb + (size_t)slot*64;
            #pragma unroll
            for (int nf = 0; nf < 4; nf++){
                #pragma unroll
                for (int p = 0; p < 2; p++){
                    int c = wn*32 + nf*8 + 2*tg + p;
                    float v = acc[mf][nf][h*2 + p];
                    bool keep = (mode == 1)
                        ? (a == 0 ? (c < 32) : (c >= 32))
                        : ((c < 16 && a == 0) || (c >= 16 && c < 32 && a == 1));
                    orow[c] = __float2half(keep ? sc*v : 0.f);
                }
            }
        }
    }
}

// ---------------- GEMM1 fill ----------------
__device__ __forceinline__ void fill1(uint32_t smb, int s, int kc, int tid,
                                      int e, int m0, int j064)
{
    uint32_t ab = smb + s*STAGEB;
    uint32_t bb = ab + 16384;
    #pragma unroll
    for (int q = 0; q < 4; q++){
        int G = tid + 256*q; int row = G >> 3, gr = G & 7;
        uint32_t off = row*128 + ((gr ^ (row & 7)) << 4);
        const __half* sa = (kc < 16)
            ? g_xg_h + (size_t)(m0 + row)*HID + kc*64 + gr*8
            : g_zgu_h + (size_t)(m0 + row)*64 + gr*8;
        cpa16(ab + off, sa);
        const __half* sb;
        if (kc < 16){
            int sr = ((row & 1) ? ITR : 0) + j064 + (row >> 1);
            sb = g_wgu_h + ((size_t)e*(2*ITR) + sr)*HID + kc*64 + gr*8;
        } else {
            sb = g_bg_ext + ((size_t)e*(2*ITR) + 2*j064 + row)*64 + gr*8;
        }
        cpa16(bb + off, sb);
    }
}

// ---------------- GEMM1: fused gate/up + LoRA + SiLU -> g_act_h; extra y-blocks convert Wd ----------------
__global__ __launch_bounds__(256, 2) void k_gemm1(const float* __restrict__ wd)
{
    int t = blockIdx.x;
    if (blockIdx.y >= NCT1){
        // conversion workers: fp32 Wd -> fp16
        size_t wi = ((size_t)(blockIdx.y - NCT1)*MAXT + t)*blockDim.x + threadIdx.x;
        size_t nw = (size_t)NEY*MAXT*blockDim.x;
        const size_t n2 = (size_t)NEXP*HID*ITR/4;
        __half2* o2 = (__half2*)g_wd_h;
        for (size_t i = wi; i < n2; i += nw){
            float4 v = ((const float4*)wd)[i];
            o2[2*i]   = __float22half2_rn(make_float2(v.x, v.y));
            o2[2*i+1] = __float22half2_rn(make_float2(v.z, v.w));
        }
        return;
    }
    if (t >= g2_ntiles) return;
    int e = g2_e[t], m0 = g2_m0[t], rows = g2_rows[t];
    int j064 = blockIdx.y * 64;

    extern __shared__ char smc[];
    uint32_t smb = s2u(smc);
    int tid = threadIdx.x, lane = tid & 31, wid = tid >> 5;
    int wm = wid & 1, wn = wid >> 1;

    float acc[4][4][4];
    #pragma unroll
    for (int i = 0; i < 4; i++)
        #pragma unroll
        for (int j = 0; j < 4; j++)
            #pragma unroll
            for (int k = 0; k < 4; k++) acc[i][j][k] = 0.f;

    fill1(smb, 0, 0, tid, e, m0, j064); cp_commit();
    fill1(smb, 1, 1, tid, e, m0, j064); cp_commit();
    int sC = 0, sF = 2;
    for (int kc = 0; kc < NK1; kc++){
        cp_wait1();
        __syncthreads();
        if (kc + 2 < NK1){ fill1(smb, sF, kc + 2, tid, e, m0, j064); }
        cp_commit();
        uint32_t st = smb + sC*STAGEB;
        stage_mma(st, st + 16384, lane, wm, wn, acc);
        sC = (sC == 2) ? 0 : sC + 1;
        sF = (sF == 2) ? 0 : sF + 1;
    }

    int g = lane >> 2, tg = lane & 3;
    #pragma unroll
    for (int mf = 0; mf < 4; mf++){
        #pragma unroll
        for (int h = 0; h < 2; h++){
            int row = wm*64 + mf*16 + g + h*8;
            if (row >= rows) continue;
            __half* arow = g_act_h + (size_t)(m0 + row)*ITR + j064;
            #pragma unroll
            for (int nf = 0; nf < 4; nf++){
                float gate = acc[mf][nf][h*2 + 0];
                float up   = acc[mf][nf][h*2 + 1];
                float act = gate / (1.f + __expf(-gate)) * up;
                arow[wn*16 + nf*4 + tg] = __float2half(act);
            }
        }
    }
}

// ---------------- GEMM2 fill ----------------
__device__ __forceinline__ void fill2(uint32_t smb, int s, int kc, int tid,
                                      int e, int m0, int j0)
{
    uint32_t ab = smb + s*STAGEB;
    uint32_t bb = ab + 16384;
    #pragma unroll
    for (int q = 0; q < 4; q++){
        int G = tid + 256*q; int row = G >> 3, gr = G & 7;
        uint32_t off = row*128 + ((gr ^ (row & 7)) << 4);
        const __half* sa = (kc < 44)
            ? g_act_h + (size_t)(m0 + row)*ITR + kc*64 + gr*8
            : g_zd_h + (size_t)(m0 + row)*64 + gr*8;
        cpa16(ab + off, sa);
        const __half* sb = (kc < 44)
            ? g_wd_h + ((size_t)e*HID + j0 + row)*ITR + kc*64 + gr*8
            : g_bd_ext + ((size_t)e*HID + j0 + row)*64 + gr*8;
        cpa16(bb + off, sb);
    }
}

// ---------------- GEMM2: down proj + LoRA, weighted, atomic into out ----------------
__global__ __launch_bounds__(256, 2) void k_gemm2(float* __restrict__ out)
{
    int t = blockIdx.x;
    if (t >= g2_ntiles) return;
    int e = g2_e[t], m0 = g2_m0[t], rows = g2_rows[t];
    int j0 = blockIdx.y * BN;

    extern __shared__ char smc[];
    uint32_t smb = s2u(smc);
    __shared__ float s_wt[BM];
    __shared__ int   s_tok[BM];
    int tid = threadIdx.x, lane = tid & 31, wid = tid >> 5;
    int wm = wid & 1, wn = wid >> 1;
    if (tid < BM){
        int s = min(m0 + tid, NPAIR - 1);
        s_wt[tid] = g_w[s]; s_tok[tid] = g_tok[s];
    }

    float acc[4][4][4];
    #pragma unroll
    for (int i = 0; i < 4; i++)
        #pragma unroll
        for (int j = 0; j < 4; j++)
            #pragma unroll
            for (int k = 0; k < 4; k++) acc[i][j][k] = 0.f;

    fill2(smb, 0, 0, tid, e, m0, j0); cp_commit();
    fill2(smb, 1, 1, tid, e, m0, j0); cp_commit();
    int sC = 0, sF = 2;
    for (int kc = 0; kc < NK2; kc++){
        cp_wait1();
        __syncthreads();
        if (kc + 2 < NK2){ fill2(smb, sF, kc + 2, tid, e, m0, j0); }
        cp_commit();
        uint32_t st = smb + sC*STAGEB;
        stage_mma(st, st + 16384, lane, wm, wn, acc);
        sC = (sC == 2) ? 0 : sC + 1;
        sF = (sF == 2) ? 0 : sF + 1;
    }

    int g = lane >> 2, tg = lane & 3;
    #pragma unroll
    for (int mf = 0; mf < 4; mf++){
        #pragma unroll
        for (int h = 0; h < 2; h++){
            int row = wm*64 + mf*16 + g + h*8;
            if (row >= rows) continue;
            float w = s_wt[row];
            float* orow = out + (size_t)s_tok[row]*HID + j0;
            #pragma unroll
            for (int nf = 0; nf < 4; nf++){
                int c = wn*32 + nf*8 + 2*tg;
                atomicAdd(orow + c,     w * acc[mf][nf][h*2 + 0]);
                atomicAdd(orow + c + 1, w * acc[mf][nf][h*2 + 1]);
            }
        }
    }
}

// ---------------- launch ----------------
extern "C" void kernel_launch(void* const* d_in, const int* in_sizes, int n_in,
                              void* d_out, int out_size)
{
    const float* x        = (const float*)d_in[0];
    const int*   topk_ids = (const int*)  d_in[1];
    const float* topk_w   = (const float*)d_in[2];
    const float* gate_a   = (const float*)d_in[3];
    const float* gate_b   = (const float*)d_in[4];
    const float* up_a     = (const float*)d_in[5];
    const float* up_b     = (const float*)d_in[6];
    const float* down_a   = (const float*)d_in[7];
    const float* down_b   = (const float*)d_in[8];
    const int*   widx     = (const int*)  d_in[9];
    const int*   seq_lens = (const int*)  d_in[10];
    const int*   ranks    = (const int*)  d_in[11];
    const float* scalings = (const float*)d_in[12];
    const float* Wgu      = (const float*)d_in[13];
    const float* Wd       = (const float*)d_in[14];
    float* out = (float*)d_out;

    static int s_attr_done = 0;
    if (!s_attr_done){
        cudaFuncSetAttribute(k_gemm1, cudaFuncAttributeMaxDynamicSharedMemorySize, SMEM_DYN);
        cudaFuncSetAttribute(k_gemm2, cudaFuncAttributeMaxDynamicSharedMemorySize, SMEM_DYN);
        cudaFuncSetAttribute(k_loraA, cudaFuncAttributeMaxDynamicSharedMemorySize, LSMEM);
        s_attr_done = 1;
    }

    k_setup<<<1, 256>>>(topk_ids, topk_w, widx, seq_lens, scalings);
    k_preall<<<2048, 256>>>(x, gate_a, up_a, down_a,
                            gate_b, up_b, down_b, ranks, out);
    k_loraA<<<MAXT + NCV1, 256, LSMEM>>>(1, Wgu);
    k_gemm1<<<dim3(MAXT, NCT1 + NEY), 256, SMEM_DYN>>>(Wd);
    k_loraA<<<MAXT, 256, LSMEM>>>(2, Wgu);
    k_gemm2<<<dim3(MAXT, NCT2), 256, SMEM_DYN>>>(out);
}